// round 1
// baseline (speedup 1.0000x reference)
#include <cuda_runtime.h>
#include <cstdint>

// Problem constants
#define BB   32
#define CC   64
#define TT   12
#define T2   10
#define NN   883
#define KK   2649          // 3*NN
#define KPAD 2656          // 166 * 16
#define MPAD 896           // 7 * 128
#define NT   166           // K tiles
#define HTOT (BB*CC*TT*NN) // 21,706,752

// Scratch (static device allocations are allowed)
__device__ float g_H[HTOT];
__device__ float g_adjT[KPAD * MPAD];

using u64 = unsigned long long;

__device__ __forceinline__ u64 ffma2(u64 a, u64 b, u64 c) {
    u64 d;
    asm("fma.rn.f32x2 %0, %1, %2, %3;" : "=l"(d) : "l"(a), "l"(b), "l"(c));
    return d;
}
__device__ __forceinline__ u64 pack2(float x, float y) {
    u64 r;
    asm("mov.b64 %0, {%1, %2};" : "=l"(r) : "f"(x), "f"(y));
    return r;
}
__device__ __forceinline__ float2 unpack2(u64 v) {
    float2 f;
    asm("mov.b64 {%0, %1}, %2;" : "=f"(f.x), "=f"(f.y) : "l"(v));
    return f;
}
__device__ __forceinline__ float sigmoidf(float x) {
    return __fdividef(1.f, 1.f + __expf(-x));
}

// ---------------------------------------------------------------------------
// Kernel 1: H = x + temporal_emb + spatial_emb     [B,C,T,N]
// ---------------------------------------------------------------------------
__global__ void prep_h_kernel(const float* __restrict__ x,
                              const float* __restrict__ te,
                              const float* __restrict__ se) {
    int idx = blockIdx.x * blockDim.x + threadIdx.x;
    if (idx < HTOT) {
        int n = idx % NN;
        int q = idx / NN;
        int t = q % TT;
        int c = (q / TT) % CC;
        g_H[idx] = x[idx] + te[c * TT + t] + se[c * NN + n];
    }
}

// ---------------------------------------------------------------------------
// Kernel 2: adjT[k][m] = adj[m+NN][k] for k<KK, m<NN; zero-padded elsewhere.
// Shared-tile transpose, coalesced both ways.
// ---------------------------------------------------------------------------
__global__ void prep_adjT_kernel(const float* __restrict__ adj) {
    __shared__ float s[32][33];
    int mr = blockIdx.x * 32 + threadIdx.y;
    int kr = blockIdx.y * 32 + threadIdx.x;
    float v = 0.f;
    if (mr < NN && kr < KK) v = adj[(size_t)(NN + mr) * KK + kr];
    s[threadIdx.y][threadIdx.x] = v;
    __syncthreads();
    int kw = blockIdx.y * 32 + threadIdx.y;
    int mw = blockIdx.x * 32 + threadIdx.x;
    if (kw < KPAD && mw < MPAD)
        g_adjT[(size_t)kw * MPAD + mw] = s[threadIdx.x][threadIdx.y];
}

// ---------------------------------------------------------------------------
// Kernel 3: per (b,t) and 128-wide m tile:
//   G[64, 128] = Hwin[64, 2656] x adjT[2656, 128]      (f32x2 GEMM)
//   then fused per-branch GLU + branch max, store out[b, d, t, m].
//
// Shared layout (floats), 12288 floats = 48KB static:
//   GEMM phase:  As0[16*65]@0, As1@1040, Bs0[16*128]@2080, Bs1@4128
//   Epilogue:    Gs[64*128]@0 (aliases GEMM bufs), Wsh[64*64]@8192
// ---------------------------------------------------------------------------
#define SA0 0
#define SA1 1040
#define SB0 2080
#define SB1 4128
#define SGS 0
#define SWS 8192

__global__ __launch_bounds__(256, 2)
void stsgcl_main_kernel(const float* __restrict__ Wp,
                        const float* __restrict__ bias,
                        float* __restrict__ out) {
    __shared__ float smem[12288];

    const int tid = threadIdx.x;
    const int tx  = tid & 15;       // m micro-tile (8 cols)
    const int ty  = tid >> 4;       // c micro-tile (4 rows)
    const int m0  = blockIdx.x * 128;
    const int bt  = blockIdx.y;
    const int b   = bt / T2;
    const int t   = bt % T2;

    // ---- global pointers for tile loading ----
    const float* ap[4];
#pragma unroll
    for (int r = 0; r < 4; r++) {
        int c = (tid >> 4) + 16 * r;
        ap[r] = g_H + ((size_t)(b * CC + c) * TT + t) * NN + (tid & 15);
    }
    const float* bp = g_adjT + (size_t)(tid >> 5) * MPAD + m0 + (tid & 31) * 4;

    // ---- initial tile into buffer 0 ----
    {
        float* sA = smem + SA0;
        float* sB = smem + SB0;
#pragma unroll
        for (int r = 0; r < 4; r++)
            sA[(tid & 15) * 65 + ((tid >> 4) + 16 * r)] = ap[r][0];
        *(float4*)(sB + (tid >> 5) * 128 + (tid & 31) * 4) = *(const float4*)bp;
        *(float4*)(sB + ((tid >> 5) + 8) * 128 + (tid & 31) * 4) =
            *(const float4*)(bp + 8 * MPAD);
    }
    __syncthreads();

    u64 acc[4][4] = {};
    int cur = 0;

    for (int kt = 0; kt < NT; kt++) {
        float  pa[4];
        float4 pb0, pb1;
        const bool pf = (kt + 1 < NT);
        if (pf) {
#pragma unroll
            for (int r = 0; r < 4; r++) { ap[r] += 16; pa[r] = ap[r][0]; }
            bp += 16 * MPAD;
            pb0 = *(const float4*)bp;
            pb1 = *(const float4*)(bp + 8 * MPAD);
        }

        const float* sA = smem + (cur ? SA1 : SA0);
        const float* sB = smem + (cur ? SB1 : SB0);
#pragma unroll
        for (int kk = 0; kk < 16; kk++) {
            u64 aa[4], bb[4];
#pragma unroll
            for (int i = 0; i < 4; i++) {
                float av = sA[kk * 65 + ty * 4 + i];
                aa[i] = pack2(av, av);
            }
            const u64* br = (const u64*)(sB + kk * 128);
#pragma unroll
            for (int p = 0; p < 4; p++) bb[p] = br[tx * 4 + p];
#pragma unroll
            for (int i = 0; i < 4; i++)
#pragma unroll
                for (int p = 0; p < 4; p++)
                    acc[i][p] = ffma2(aa[i], bb[p], acc[i][p]);
        }

        if (pf) {
            float* dA = smem + (cur ? SA0 : SA1);
            float* dB = smem + (cur ? SB0 : SB1);
#pragma unroll
            for (int r = 0; r < 4; r++)
                dA[(tid & 15) * 65 + ((tid >> 4) + 16 * r)] = pa[r];
            *(float4*)(dB + (tid >> 5) * 128 + (tid & 31) * 4) = pb0;
            *(float4*)(dB + ((tid >> 5) + 8) * 128 + (tid & 31) * 4) = pb1;
        }
        __syncthreads();
        cur ^= 1;
    }

    // ---- stage G tile to shared (aliases GEMM buffers; all compute done) ----
    {
        float* Gs = smem + SGS;
#pragma unroll
        for (int i = 0; i < 4; i++) {
            u64* row = (u64*)(Gs + (ty * 4 + i) * 128 + tx * 8);
#pragma unroll
            for (int p = 0; p < 4; p++) row[p] = acc[i][p];
        }
    }

    // ---- fused GLU epilogue: z = W^T G + b; out = max_g( z_lin * sig(z_gate) )
    float omax[4][8];
#pragma unroll
    for (int i = 0; i < 4; i++)
#pragma unroll
        for (int j = 0; j < 8; j++) omax[i][j] = -3.4e38f;

    const float* Gs  = smem + SGS;
    float*       Wsh = smem + SWS;

    for (int g = 0; g < 3; g++) {
        for (int h = 0; h < 2; h++) {
            __syncthreads();   // protect Wsh (and first pass: Gs) before reload
            // Wsh[c*64 + j]: j<32 -> lin d = h*32+j ; j>=32 -> gate d = 64+h*32+(j-32)
#pragma unroll
            for (int q = 0; q < 16; q++) {
                int lin = tid + 256 * q;
                int c   = lin >> 6;
                int j   = lin & 63;
                int dg  = (j < 32) ? (h * 32 + j) : (64 + h * 32 + (j - 32));
                Wsh[lin] = Wp[(g * CC + c) * 128 + dg];
            }
            __syncthreads();

            const int d0 = h * 32 + ty * 2;
            float bl0 = bias[g * 128 + d0],      bl1 = bias[g * 128 + d0 + 1];
            float bg0 = bias[g * 128 + 64 + d0], bg1 = bias[g * 128 + 64 + d0 + 1];
            u64 zl[2][4], zg[2][4];
#pragma unroll
            for (int p = 0; p < 4; p++) {
                zl[0][p] = pack2(bl0, bl0); zl[1][p] = pack2(bl1, bl1);
                zg[0][p] = pack2(bg0, bg0); zg[1][p] = pack2(bg1, bg1);
            }

#pragma unroll 4
            for (int c = 0; c < 64; c++) {
                const u64* gr = (const u64*)(Gs + c * 128 + tx * 8);
                u64 gg[4];
#pragma unroll
                for (int p = 0; p < 4; p++) gg[p] = gr[p];
                float wl0 = Wsh[c * 64 + ty * 2];
                float wl1 = Wsh[c * 64 + ty * 2 + 1];
                float wg0 = Wsh[c * 64 + 32 + ty * 2];
                float wg1 = Wsh[c * 64 + 32 + ty * 2 + 1];
                u64 wl2[2] = { pack2(wl0, wl0), pack2(wl1, wl1) };
                u64 wg2[2] = { pack2(wg0, wg0), pack2(wg1, wg1) };
#pragma unroll
                for (int il = 0; il < 2; il++)
#pragma unroll
                    for (int p = 0; p < 4; p++) {
                        zl[il][p] = ffma2(wl2[il], gg[p], zl[il][p]);
                        zg[il][p] = ffma2(wg2[il], gg[p], zg[il][p]);
                    }
            }

#pragma unroll
            for (int il = 0; il < 2; il++) {
                int ii = h * 2 + il;
#pragma unroll
                for (int p = 0; p < 4; p++) {
                    float2 L  = unpack2(zl[il][p]);
                    float2 Gt = unpack2(zg[il][p]);
                    float v0 = L.x * sigmoidf(Gt.x);
                    float v1 = L.y * sigmoidf(Gt.y);
                    omax[ii][2 * p]     = fmaxf(omax[ii][2 * p],     v0);
                    omax[ii][2 * p + 1] = fmaxf(omax[ii][2 * p + 1], v1);
                }
            }
        }
    }

    // ---- store out[b, d, t, m] ----
#pragma unroll
    for (int i = 0; i < 4; i++) {
        int d = (i >> 1) * 32 + ty * 2 + (i & 1);
        size_t obase = ((size_t)(b * CC + d) * T2 + t) * NN;
#pragma unroll
        for (int j = 0; j < 8; j++) {
            int m = m0 + tx * 8 + j;
            if (m < NN) out[obase + m] = omax[i][j];
        }
    }
}

// ---------------------------------------------------------------------------
extern "C" void kernel_launch(void* const* d_in, const int* in_sizes, int n_in,
                              void* d_out, int out_size) {
    const float* x    = (const float*)d_in[0];
    const float* te   = (const float*)d_in[1];
    const float* se   = (const float*)d_in[2];
    const float* adj  = (const float*)d_in[3];
    const float* Wp   = (const float*)d_in[4];
    const float* bias = (const float*)d_in[5];
    float* out = (float*)d_out;

    prep_h_kernel<<<(HTOT + 255) / 256, 256>>>(x, te, se);

    dim3 tgrid(MPAD / 32, KPAD / 32);   // (28, 83)
    prep_adjT_kernel<<<tgrid, dim3(32, 32)>>>(adj);

    dim3 grid(MPAD / 128, BB * T2);     // (7, 320)
    stsgcl_main_kernel<<<grid, 256>>>(Wp, bias, out);
}

// round 3
// speedup vs baseline: 2.7943x; 2.7943x over previous
#include <cuda_runtime.h>
#include <cuda_bf16.h>
#include <cstdint>

// ---------------- problem constants ----------------
#define BB   32
#define CCH  64
#define TT   12
#define T2   10
#define NN   883
#define NP   896            // padded vertex count
#define KP   2688           // 3*NP padded K
#define NKT  42             // K tiles of 64
#define NPAIR 160           // 320 (b,t) / 2
#define HP_ELEMS  (BB*CCH*TT*NP)   // 22,020,096
#define BADJ_ELEMS ((size_t)NP*KP) // 2,408,448

__device__ __nv_bfloat16 g_Ahi[HP_ELEMS];
__device__ __nv_bfloat16 g_Alo[HP_ELEMS];
__device__ __nv_bfloat16 g_Bhi[BADJ_ELEMS];
__device__ __nv_bfloat16 g_Blo[BADJ_ELEMS];

using u64 = unsigned long long;

__device__ __forceinline__ uint32_t smem_u32_of(const void* p) {
    uint32_t a;
    asm("{ .reg .u64 t; cvta.to.shared.u64 t, %1; cvt.u32.u64 %0, t; }" : "=r"(a) : "l"(p));
    return a;
}
__device__ __forceinline__ u64 ffma2(u64 a, u64 b, u64 c) {
    u64 d; asm("fma.rn.f32x2 %0, %1, %2, %3;" : "=l"(d) : "l"(a), "l"(b), "l"(c)); return d;
}
__device__ __forceinline__ u64 pack2(float x, float y) {
    u64 r; asm("mov.b64 %0, {%1, %2};" : "=l"(r) : "f"(x), "f"(y)); return r;
}
__device__ __forceinline__ float2 unpack2(u64 v) {
    float2 f; asm("mov.b64 {%0, %1}, %2;" : "=f"(f.x), "=f"(f.y) : "l"(v)); return f;
}
__device__ __forceinline__ float sigmoidf(float x) {
    return __fdividef(1.f, 1.f + __expf(-x));
}
#define SW128(o) ((o) ^ (((o) >> 3) & 0x70))

// cp.async
__device__ __forceinline__ void cpa16(uint32_t dst, const void* src) {
    asm volatile("cp.async.cg.shared.global [%0], [%1], 16;" :: "r"(dst), "l"(src));
}
__device__ __forceinline__ void cpa_commit() { asm volatile("cp.async.commit_group;" ::: "memory"); }
template<int N> __device__ __forceinline__ void cpa_wait() {
    asm volatile("cp.async.wait_group %0;" :: "n"(N) : "memory");
}

// warp-level tensor ops (baseline PTX, compiles for compute_103)
__device__ __forceinline__ void ldm4(uint32_t* r, uint32_t addr) {
    asm volatile("ldmatrix.sync.aligned.m8n8.x4.shared.b16 {%0,%1,%2,%3}, [%4];"
                 : "=r"(r[0]), "=r"(r[1]), "=r"(r[2]), "=r"(r[3]) : "r"(addr));
}
__device__ __forceinline__ void mma16816(float* d, const uint32_t* a, const uint32_t* b) {
    asm volatile("mma.sync.aligned.m16n8k16.row.col.f32.bf16.bf16.f32 "
                 "{%0,%1,%2,%3}, {%4,%5,%6,%7}, {%8,%9}, {%0,%1,%2,%3};"
                 : "+f"(d[0]), "+f"(d[1]), "+f"(d[2]), "+f"(d[3])
                 : "r"(a[0]), "r"(a[1]), "r"(a[2]), "r"(a[3]), "r"(b[0]), "r"(b[1]));
}

// ---------------------------------------------------------------------------
// prep 1: padded split-H  hi/lo[b][c][t][896]
// ---------------------------------------------------------------------------
__global__ void prep_split_h(const float* __restrict__ x,
                             const float* __restrict__ te,
                             const float* __restrict__ se) {
    int idx = blockIdx.x * blockDim.x + threadIdx.x;
    if (idx >= HP_ELEMS) return;
    int n = idx % NP;
    int q = idx / NP;
    int t = q % TT;
    int c = (q / TT) % CCH;
    int b = q / (TT * CCH);
    float v = 0.f;
    if (n < NN)
        v = x[((size_t)(b * CCH + c) * TT + t) * NN + n] + te[c * TT + t] + se[c * NN + n];
    __nv_bfloat16 hi = __float2bfloat16(v);
    __nv_bfloat16 lo = __float2bfloat16(v - __bfloat162float(hi));
    g_Ahi[idx] = hi;
    g_Alo[idx] = lo;
}

// ---------------------------------------------------------------------------
// prep 2: split-B  [m=896][k=2688]: row m = adj[NN+m], 3 zero-padded k blocks
// ---------------------------------------------------------------------------
__global__ void prep_split_b(const float* __restrict__ adj) {
    size_t idx = (size_t)blockIdx.x * blockDim.x + threadIdx.x;
    if (idx >= BADJ_ELEMS) return;
    int kc = (int)(idx % KP);
    int m  = (int)(idx / KP);
    int j  = kc / NP;
    int kk = kc % NP;
    float v = 0.f;
    if (m < NN && kk < NN)
        v = adj[(size_t)(NN + m) * (3 * NN) + j * NN + kk];
    __nv_bfloat16 hi = __float2bfloat16(v);
    __nv_bfloat16 lo = __float2bfloat16(v - __bfloat162float(hi));
    g_Bhi[idx] = hi;
    g_Blo[idx] = lo;
}

// ---------------------------------------------------------------------------
// main: warp-MMA split-bf16 GEMM + fused GLU epilogue
//   CTA = (m-tile of 128, bt-pair): D[128, 128] fp32 across 8 warps (64x32 each)
// SMEM: 3 stages x 64KB; per stage: Ahi(16K) Alo(16K) Bhi(16K) Blo(16K),
//       128B SW128 rows of 64 bf16.
// Epilogue reuses smem: Gs[128][130] f32 + Wsh[64][64] f32
// ---------------------------------------------------------------------------
#define STAGE_BYTES 65536
#define DSMEM_BYTES (3 * STAGE_BYTES)
#define GSTR 130

__global__ __launch_bounds__(256, 1)
void stsgcl_mma_kernel(const float* __restrict__ Wp,
                       const float* __restrict__ bias,
                       float* __restrict__ out) {
    extern __shared__ char dsm[];

    const int tid = threadIdx.x;
    const int m0  = blockIdx.x * 128;
    const int p   = blockIdx.y;
    const int bt0 = 2 * p;
    const int b   = bt0 / T2;
    const int t0  = bt0 % T2;

    const uint32_t smem = smem_u32_of(dsm);

    // ---- per-thread loader precompute: 16 chunks of 16B per stage ----
    const char* src0[16];
    uint32_t    dsto[16];
#pragma unroll
    for (int i = 0; i < 16; i++) {
        int L    = tid + 256 * i;
        int tile = L >> 10;        // 0:Ahi 1:Alo 2:Bhi 3:Blo
        int r    = (L >> 3) & 127;
        int c16  = L & 7;
        if (tile < 2) {
            int cch = r & 63;
            int tt  = t0 + (r >> 6);
            size_t e = ((size_t)(b * CCH + cch) * TT + tt) * NP + c16 * 8;
            src0[i] = (const char*)((tile == 0) ? g_Ahi : g_Alo) + e * 2;
        } else {
            size_t e = (size_t)(m0 + r) * KP + c16 * 8;
            src0[i] = (const char*)((tile == 2) ? g_Bhi : g_Blo) + e * 2;
        }
        dsto[i] = tile * 16384 + SW128(r * 128 + c16 * 16);
    }

    // ---- prologue: load stages 0,1,2 ----
#pragma unroll
    for (int s = 0; s < 3; s++) {
        uint32_t sb = smem + s * STAGE_BYTES;
#pragma unroll
        for (int i = 0; i < 16; i++) cpa16(sb + dsto[i], src0[i] + (size_t)s * 128);
        cpa_commit();
    }

    // ---- MMA setup ----
    const int lane = tid & 31;
    const int wid  = tid >> 5;
    const int wm   = wid & 1;       // m half (64 rows)
    const int wn   = wid >> 1;      // n quarter (32 cols)
    const int rsel = lane & 7;
    const int tsel = lane >> 3;

    // A fragment addressing (m16k16 via ldmatrix.x4)
    const int aRowBase = wm * 64 + ((tsel & 1) << 3) + rsel;  // + mf*16
    const uint32_t kbeA = (uint32_t)((tsel >> 1) << 4);
    const uint32_t aswz = (uint32_t)((aRowBase & 7) << 4);
    uint32_t aoff[4];
#pragma unroll
    for (int mf = 0; mf < 4; mf++) aoff[mf] = (uint32_t)((aRowBase + mf * 16) * 128);

    // B fragment addressing (two n8k16 frags per ldmatrix.x4)
    const int bRowBase = wn * 32 + ((tsel >> 1) << 3) + rsel; // + nf2*16
    const uint32_t kbeB = (uint32_t)((tsel & 1) << 4);
    const uint32_t bswz = (uint32_t)((bRowBase & 7) << 4);
    uint32_t boff[2];
#pragma unroll
    for (int nf2 = 0; nf2 < 2; nf2++) boff[nf2] = (uint32_t)((bRowBase + nf2 * 16) * 128);

    float d[4][4][4];
#pragma unroll
    for (int i = 0; i < 4; i++)
#pragma unroll
        for (int j = 0; j < 4; j++)
#pragma unroll
            for (int q = 0; q < 4; q++) d[i][j][q] = 0.f;

    // ---- main K loop ----
    for (int kt = 0; kt < NKT; kt++) {
        const int s = kt % 3;
        if (kt <= NKT - 3)      cpa_wait<2>();
        else if (kt == NKT - 2) cpa_wait<1>();
        else                    cpa_wait<0>();
        __syncthreads();

        const uint32_t sb = smem + s * STAGE_BYTES;
#pragma unroll
        for (int ks = 0; ks < 4; ks++) {
            const uint32_t kb = (uint32_t)(ks * 32);
            uint32_t a_hi[4][4], a_lo[4][4];
#pragma unroll
            for (int mf = 0; mf < 4; mf++) {
                uint32_t addr = sb + aoff[mf] + ((kb + kbeA) ^ aswz);
                ldm4(a_hi[mf], addr);
                ldm4(a_lo[mf], addr + 16384);
            }
            uint32_t b_hi[4][2], b_lo[4][2];
#pragma unroll
            for (int nf2 = 0; nf2 < 2; nf2++) {
                uint32_t addr = sb + 32768 + boff[nf2] + ((kb + kbeB) ^ bswz);
                uint32_t tmp[4];
                ldm4(tmp, addr);
                b_hi[2 * nf2][0] = tmp[0]; b_hi[2 * nf2][1] = tmp[1];
                b_hi[2 * nf2 + 1][0] = tmp[2]; b_hi[2 * nf2 + 1][1] = tmp[3];
                ldm4(tmp, addr + 16384);
                b_lo[2 * nf2][0] = tmp[0]; b_lo[2 * nf2][1] = tmp[1];
                b_lo[2 * nf2 + 1][0] = tmp[2]; b_lo[2 * nf2 + 1][1] = tmp[3];
            }
#pragma unroll
            for (int mf = 0; mf < 4; mf++)
#pragma unroll
                for (int nf = 0; nf < 4; nf++) {
                    mma16816(d[mf][nf], a_hi[mf], b_hi[nf]);
                    mma16816(d[mf][nf], a_hi[mf], b_lo[nf]);
                    mma16816(d[mf][nf], a_lo[mf], b_hi[nf]);
                }
        }
        __syncthreads();

        if (kt <= NKT - 4) {
            size_t koff = (size_t)(kt + 3) * 128;
#pragma unroll
            for (int i = 0; i < 16; i++) cpa16(sb + dsto[i], src0[i] + koff);
            cpa_commit();
        }
    }

    // ---- store accumulators -> Gs[128][130] ----
    {
        float* Gs = (float*)dsm;
        const int grp = lane >> 2;
        const int thr = lane & 3;
#pragma unroll
        for (int mf = 0; mf < 4; mf++)
#pragma unroll
            for (int nf = 0; nf < 4; nf++) {
                int row = wm * 64 + mf * 16 + grp;
                int col = wn * 32 + nf * 8 + thr * 2;
                float* p0 = Gs + row * GSTR + col;
                p0[0] = d[mf][nf][0];
                p0[1] = d[mf][nf][1];
                float* p1 = p0 + 8 * GSTR;
                p1[0] = d[mf][nf][2];
                p1[1] = d[mf][nf][3];
            }
    }
    __syncthreads();

    // ---- scalar GLU epilogue (f32x2), two bt passes ----
    const int tx = tid & 15;
    const int ty = tid >> 4;
    float* Gsf = (float*)dsm;
    float* Wsh = Gsf + 128 * GSTR;

    for (int bsel = 0; bsel < 2; bsel++) {
        const float* Gb = Gsf + bsel * 64 * GSTR;
        float omax[4][8];
#pragma unroll
        for (int i = 0; i < 4; i++)
#pragma unroll
            for (int j = 0; j < 8; j++) omax[i][j] = -3.4e38f;

        for (int g = 0; g < 3; g++) {
            for (int h = 0; h < 2; h++) {
                __syncthreads();
#pragma unroll
                for (int q = 0; q < 16; q++) {
                    int lin = tid + 256 * q;
                    int c   = lin >> 6;
                    int j   = lin & 63;
                    int dg  = (j < 32) ? (h * 32 + j) : (64 + h * 32 + (j - 32));
                    Wsh[lin] = Wp[(g * CCH + c) * 128 + dg];
                }
                __syncthreads();

                const int d0 = h * 32 + ty * 2;
                float bl0 = bias[g * 128 + d0],      bl1 = bias[g * 128 + d0 + 1];
                float bg0 = bias[g * 128 + 64 + d0], bg1 = bias[g * 128 + 64 + d0 + 1];
                u64 zl[2][4], zg[2][4];
#pragma unroll
                for (int pq = 0; pq < 4; pq++) {
                    zl[0][pq] = pack2(bl0, bl0); zl[1][pq] = pack2(bl1, bl1);
                    zg[0][pq] = pack2(bg0, bg0); zg[1][pq] = pack2(bg1, bg1);
                }
#pragma unroll 4
                for (int c = 0; c < 64; c++) {
                    const u64* gr = (const u64*)(Gb + c * GSTR + tx * 8);
                    u64 gg[4];
#pragma unroll
                    for (int pq = 0; pq < 4; pq++) gg[pq] = gr[pq];
                    float wl0 = Wsh[c * 64 + ty * 2];
                    float wl1 = Wsh[c * 64 + ty * 2 + 1];
                    float wg0 = Wsh[c * 64 + 32 + ty * 2];
                    float wg1 = Wsh[c * 64 + 32 + ty * 2 + 1];
                    u64 wl2[2] = { pack2(wl0, wl0), pack2(wl1, wl1) };
                    u64 wg2[2] = { pack2(wg0, wg0), pack2(wg1, wg1) };
#pragma unroll
                    for (int il = 0; il < 2; il++)
#pragma unroll
                        for (int pq = 0; pq < 4; pq++) {
                            zl[il][pq] = ffma2(wl2[il], gg[pq], zl[il][pq]);
                            zg[il][pq] = ffma2(wg2[il], gg[pq], zg[il][pq]);
                        }
                }
#pragma unroll
                for (int il = 0; il < 2; il++) {
                    int ii = h * 2 + il;
#pragma unroll
                    for (int pq = 0; pq < 4; pq++) {
                        float2 L  = unpack2(zl[il][pq]);
                        float2 Gt = unpack2(zg[il][pq]);
                        float v0 = L.x * sigmoidf(Gt.x);
                        float v1 = L.y * sigmoidf(Gt.y);
                        omax[ii][2 * pq]     = fmaxf(omax[ii][2 * pq],     v0);
                        omax[ii][2 * pq + 1] = fmaxf(omax[ii][2 * pq + 1], v1);
                    }
                }
            }
        }

        const int bt = bt0 + bsel;
        const int tb = bt % T2;
#pragma unroll
        for (int i = 0; i < 4; i++) {
            int dd = (i >> 1) * 32 + ty * 2 + (i & 1);
            size_t obase = ((size_t)(b * CCH + dd) * T2 + tb) * NN;
#pragma unroll
            for (int j = 0; j < 8; j++) {
                int m = m0 + tx * 8 + j;
                if (m < NN) out[obase + m] = omax[i][j];
            }
        }
    }
}

// ---------------------------------------------------------------------------
extern "C" void kernel_launch(void* const* d_in, const int* in_sizes, int n_in,
                              void* d_out, int out_size) {
    const float* x    = (const float*)d_in[0];
    const float* te   = (const float*)d_in[1];
    const float* se   = (const float*)d_in[2];
    const float* adj  = (const float*)d_in[3];
    const float* Wp   = (const float*)d_in[4];
    const float* bias = (const float*)d_in[5];
    float* out = (float*)d_out;

    cudaFuncSetAttribute(stsgcl_mma_kernel,
                         cudaFuncAttributeMaxDynamicSharedMemorySize, DSMEM_BYTES);

    prep_split_h<<<(HP_ELEMS + 255) / 256, 256>>>(x, te, se);
    prep_split_b<<<(int)((BADJ_ELEMS + 255) / 256), 256>>>(adj);

    dim3 grid(NP / 128, NPAIR);   // (7, 160)
    stsgcl_mma_kernel<<<grid, 256, DSMEM_BYTES>>>(Wp, bias, out);
}

// round 5
// speedup vs baseline: 5.7231x; 2.0481x over previous
#include <cuda_runtime.h>
#include <cuda_fp16.h>
#include <cstdint>

// ---------------- problem constants ----------------
#define BB   32
#define CCH  64
#define TT   12
#define T2   10
#define NN   883
#define NP   896            // padded vertex count
#define KP   2688           // 3*NP padded K
#define NKT  42             // K tiles of 64
#define NPAIR 160
#define HP_ELEMS  (BB*CCH*TT*NP)
#define BADJ_ELEMS ((size_t)NP*KP)

__device__ __half g_Ah[HP_ELEMS];
__device__ __half g_Bhi[BADJ_ELEMS];
__device__ __half g_Blo[BADJ_ELEMS];

using u64 = unsigned long long;

__device__ __forceinline__ uint32_t smem_u32_of(const void* p) {
    uint32_t a;
    asm("{ .reg .u64 t; cvta.to.shared.u64 t, %1; cvt.u32.u64 %0, t; }" : "=r"(a) : "l"(p));
    return a;
}
__device__ __forceinline__ float sigmoidf(float x) {
    return __fdividef(1.f, 1.f + __expf(-x));
}
#define SW128(o) ((o) ^ (((o) >> 3) & 0x70))

// cp.async
__device__ __forceinline__ void cpa16(uint32_t dst, const void* src) {
    asm volatile("cp.async.cg.shared.global [%0], [%1], 16;" :: "r"(dst), "l"(src));
}
__device__ __forceinline__ void cpa_commit() { asm volatile("cp.async.commit_group;" ::: "memory"); }
template<int N> __device__ __forceinline__ void cpa_wait() {
    asm volatile("cp.async.wait_group %0;" :: "n"(N) : "memory");
}

// warp tensor ops (baseline PTX)
__device__ __forceinline__ void ldm4(uint32_t* r, uint32_t addr) {
    asm volatile("ldmatrix.sync.aligned.m8n8.x4.shared.b16 {%0,%1,%2,%3}, [%4];"
                 : "=r"(r[0]), "=r"(r[1]), "=r"(r[2]), "=r"(r[3]) : "r"(addr));
}
__device__ __forceinline__ void ldm4t(uint32_t* r, uint32_t addr) {
    asm volatile("ldmatrix.sync.aligned.m8n8.x4.trans.shared.b16 {%0,%1,%2,%3}, [%4];"
                 : "=r"(r[0]), "=r"(r[1]), "=r"(r[2]), "=r"(r[3]) : "r"(addr));
}
__device__ __forceinline__ void mma16816(float* d, const uint32_t* a, const uint32_t* b) {
    asm volatile("mma.sync.aligned.m16n8k16.row.col.f32.f16.f16.f32 "
                 "{%0,%1,%2,%3}, {%4,%5,%6,%7}, {%8,%9}, {%0,%1,%2,%3};"
                 : "+f"(d[0]), "+f"(d[1]), "+f"(d[2]), "+f"(d[3])
                 : "r"(a[0]), "r"(a[1]), "r"(a[2]), "r"(a[3]), "r"(b[0]), "r"(b[1]));
}

// ---------------------------------------------------------------------------
// prep 1: padded H -> fp16 (single rounding)
// ---------------------------------------------------------------------------
__global__ void prep_h_fp16(const float* __restrict__ x,
                            const float* __restrict__ te,
                            const float* __restrict__ se) {
    int idx = blockIdx.x * blockDim.x + threadIdx.x;
    if (idx >= HP_ELEMS) return;
    int n = idx % NP;
    int q = idx / NP;
    int t = q % TT;
    int c = (q / TT) % CCH;
    int b = q / (TT * CCH);
    float v = 0.f;
    if (n < NN)
        v = x[((size_t)(b * CCH + c) * TT + t) * NN + n] + te[c * TT + t] + se[c * NN + n];
    g_Ah[idx] = __float2half(v);
}

// ---------------------------------------------------------------------------
// prep 2: B = middle adj rows, fp16 split hi+lo, zero-padded
// ---------------------------------------------------------------------------
__global__ void prep_split_b(const float* __restrict__ adj) {
    size_t idx = (size_t)blockIdx.x * blockDim.x + threadIdx.x;
    if (idx >= BADJ_ELEMS) return;
    int kc = (int)(idx % KP);
    int m  = (int)(idx / KP);
    int j  = kc / NP;
    int kk = kc % NP;
    float v = 0.f;
    if (m < NN && kk < NN)
        v = adj[(size_t)(NN + m) * (3 * NN) + j * NN + kk];
    __half hi = __float2half(v);
    __half lo = __float2half(v - __half2float(hi));
    g_Bhi[idx] = hi;
    g_Blo[idx] = lo;
}

// ---------------------------------------------------------------------------
// main kernel
// GEMM1: D[128,128] = A(fp16)[128,2688] x (Bhi+Blo)[2688,128], 8 warps 64x32
// SMEM: 4 stages x 48KB (A 16K | Bhi 16K | Blo 16K), SW128 rows of 64 fp16
// Epilogue: Gs fp16 [128][136] + Wt fp16 [3g][lin/gate][64d][72c]; tensor GLU
// ---------------------------------------------------------------------------
#define STAGE_BYTES 49152
#define DSMEM_BYTES (4 * STAGE_BYTES)   // 196608
#define GS_STRIDE 136                   // halfs; 272B rows (17 x 16B)
#define WT_OFF 40960                    // bytes; Gs needs 34816
#define WT_DSTR 72                      // halfs; 144B rows (9 x 16B)

__global__ __launch_bounds__(256, 1)
void stsgcl_mma_kernel(const float* __restrict__ Wp,
                       const float* __restrict__ bias,
                       float* __restrict__ out) {
    extern __shared__ char dsm[];

    const int tid = threadIdx.x;
    const int m0  = blockIdx.x * 128;
    const int bt0 = 2 * blockIdx.y;
    const int b   = bt0 / T2;
    const int t0  = bt0 % T2;

    const uint32_t smem = smem_u32_of(dsm);

    // ---- loader precompute: 12 x 16B chunks per stage ----
    const char* src0[12];
    uint32_t    dsto[12];
#pragma unroll
    for (int i = 0; i < 12; i++) {
        int L    = tid + 256 * i;
        int tile = L >> 10;        // 0:A 1:Bhi 2:Blo
        int r    = (L >> 3) & 127;
        int c16  = L & 7;
        if (tile == 0) {
            int cch = r & 63;
            int tt  = t0 + (r >> 6);
            size_t e = ((size_t)(b * CCH + cch) * TT + tt) * NP + c16 * 8;
            src0[i] = (const char*)g_Ah + e * 2;
        } else {
            size_t e = (size_t)(m0 + r) * KP + c16 * 8;
            src0[i] = (const char*)((tile == 1) ? g_Bhi : g_Blo) + e * 2;
        }
        dsto[i] = tile * 16384 + SW128(r * 128 + c16 * 16);
    }

    // ---- prologue: fill 4 stages ----
#pragma unroll
    for (int s = 0; s < 4; s++) {
        uint32_t sb = smem + s * STAGE_BYTES;
#pragma unroll
        for (int i = 0; i < 12; i++) cpa16(sb + dsto[i], src0[i] + (size_t)s * 128);
        cpa_commit();
    }

    // ---- MMA setup (warp 64m x 32n of D) ----
    const int lane = tid & 31;
    const int wid  = tid >> 5;
    const int wm   = wid & 1;
    const int wn   = wid >> 1;
    const int rsel = lane & 7;
    const int tsel = lane >> 3;
    const int grp  = lane >> 2;
    const int thr  = lane & 3;

    const int aRowBase = wm * 64 + ((tsel & 1) << 3) + rsel;
    const uint32_t kbeA = (uint32_t)((tsel >> 1) << 4);
    const uint32_t aswz = (uint32_t)((aRowBase & 7) << 4);
    uint32_t aoff[4];
#pragma unroll
    for (int mf = 0; mf < 4; mf++) aoff[mf] = (uint32_t)((aRowBase + mf * 16) * 128);

    const int bRowBase = wn * 32 + ((tsel >> 1) << 3) + rsel;
    const uint32_t kbeB = (uint32_t)((tsel & 1) << 4);
    const uint32_t bswz = (uint32_t)((bRowBase & 7) << 4);
    uint32_t boff[2];
#pragma unroll
    for (int nf2 = 0; nf2 < 2; nf2++) boff[nf2] = (uint32_t)((bRowBase + nf2 * 16) * 128);

    float d[4][4][4];
#pragma unroll
    for (int i = 0; i < 4; i++)
#pragma unroll
        for (int j = 0; j < 4; j++)
#pragma unroll
            for (int q = 0; q < 4; q++) d[i][j][q] = 0.f;

    // ---- main K loop ----
    for (int kt = 0; kt < NKT; kt++) {
        if (kt <= NKT - 4)      cpa_wait<3>();
        else if (kt == NKT - 3) cpa_wait<2>();
        else if (kt == NKT - 2) cpa_wait<1>();
        else                    cpa_wait<0>();
        __syncthreads();

        const uint32_t sb = smem + (kt & 3) * STAGE_BYTES;
#pragma unroll
        for (int ks = 0; ks < 4; ks++) {
            const uint32_t kb = (uint32_t)(ks * 32);
            uint32_t a[4][4];
#pragma unroll
            for (int mf = 0; mf < 4; mf++)
                ldm4(a[mf], sb + aoff[mf] + ((kb + kbeA) ^ aswz));
            uint32_t b_hi[4][2], b_lo[4][2];
#pragma unroll
            for (int nf2 = 0; nf2 < 2; nf2++) {
                uint32_t addr = sb + 16384 + boff[nf2] + ((kb + kbeB) ^ bswz);
                uint32_t tmp[4];
                ldm4(tmp, addr);
                b_hi[2 * nf2][0] = tmp[0]; b_hi[2 * nf2][1] = tmp[1];
                b_hi[2 * nf2 + 1][0] = tmp[2]; b_hi[2 * nf2 + 1][1] = tmp[3];
                ldm4(tmp, addr + 16384);
                b_lo[2 * nf2][0] = tmp[0]; b_lo[2 * nf2][1] = tmp[1];
                b_lo[2 * nf2 + 1][0] = tmp[2]; b_lo[2 * nf2 + 1][1] = tmp[3];
            }
#pragma unroll
            for (int mf = 0; mf < 4; mf++)
#pragma unroll
                for (int nf = 0; nf < 4; nf++) {
                    mma16816(d[mf][nf], a[mf], b_hi[nf]);
                    mma16816(d[mf][nf], a[mf], b_lo[nf]);
                }
        }
        __syncthreads();

        if (kt <= NKT - 5) {
            size_t koff = (size_t)(kt + 4) * 128;
#pragma unroll
            for (int i = 0; i < 12; i++) cpa16(sb + dsto[i], src0[i] + koff);
            cpa_commit();
        }
    }

    // ---- stage G (fp16) to Gs[128][136] ----
    {
        __half* Gs = (__half*)dsm;
#pragma unroll
        for (int mf = 0; mf < 4; mf++)
#pragma unroll
            for (int nf = 0; nf < 4; nf++) {
                int row = wm * 64 + mf * 16 + grp;
                int col = wn * 32 + nf * 8 + thr * 2;
                *(__half2*)&Gs[row * GS_STRIDE + col] =
                    __floats2half2_rn(d[mf][nf][0], d[mf][nf][1]);
                *(__half2*)&Gs[(row + 8) * GS_STRIDE + col] =
                    __floats2half2_rn(d[mf][nf][2], d[mf][nf][3]);
            }
    }

    // ---- stage W^T (fp16): Wt[g][sel][d][72] with sel 0=lin 1=gate ----
    {
        __half* Wt = (__half*)(dsm + WT_OFF);
#pragma unroll
        for (int it = 0; it < 24; it++) {
            int lin = (tid + 256 * it) * 4;       // over 3*64*128 = 24576
            int g   = lin >> 13;
            int c   = (lin >> 7) & 63;
            int dd  = lin & 127;
            float4 w = *(const float4*)&Wp[((size_t)(g * CCH + c)) * 128 + dd];
            int gsel = g * 2 + (dd >> 6);
            int d0   = dd & 63;
            __half* base = Wt + (size_t)gsel * 64 * WT_DSTR + c;
            base[(d0 + 0) * WT_DSTR] = __float2half(w.x);
            base[(d0 + 1) * WT_DSTR] = __float2half(w.y);
            base[(d0 + 2) * WT_DSTR] = __float2half(w.z);
            base[(d0 + 3) * WT_DSTR] = __float2half(w.w);
        }
    }
    __syncthreads();

    // ---- tensor GLU epilogue ----
    const int dw = wid & 1;
    const int mw = wid >> 1;
    const uint32_t GsB = smem;
    const uint32_t WtB = smem + WT_OFF;

    const int aRow2 = dw * 32 + ((tsel & 1) << 3) + rsel;       // + mf*16
    const uint32_t akOff = (uint32_t)(((tsel >> 1) << 3) * 2);
    const int bkRow = ((tsel & 1) << 3) + rsel;                 // + ks*16 (+bsel*64)
    const int bmOff = mw * 32 + ((tsel >> 1) << 3);             // + mt*16

    for (int bsel = 0; bsel < 2; bsel++) {
        float omax[2][4][4];
#pragma unroll
        for (int mf = 0; mf < 2; mf++)
#pragma unroll
            for (int nf = 0; nf < 4; nf++)
#pragma unroll
                for (int q = 0; q < 4; q++) omax[mf][nf][q] = -3.4e38f;

        for (int g = 0; g < 3; g++) {
            float zl[2][4][4], zg[2][4][4];
#pragma unroll
            for (int mf = 0; mf < 2; mf++) {
                int dbase = dw * 32 + mf * 16 + grp;
                float bl0 = __ldg(&bias[g * 128 + dbase]);
                float bl8 = __ldg(&bias[g * 128 + dbase + 8]);
                float bg0 = __ldg(&bias[g * 128 + 64 + dbase]);
                float bg8 = __ldg(&bias[g * 128 + 64 + dbase + 8]);
#pragma unroll
                for (int nf = 0; nf < 4; nf++) {
                    zl[mf][nf][0] = bl0; zl[mf][nf][1] = bl0;
                    zl[mf][nf][2] = bl8; zl[mf][nf][3] = bl8;
                    zg[mf][nf][0] = bg0; zg[mf][nf][1] = bg0;
                    zg[mf][nf][2] = bg8; zg[mf][nf][3] = bg8;
                }
            }

            const uint32_t WL = WtB + (uint32_t)(g * 2) * 64 * WT_DSTR * 2;
#pragma unroll
            for (int ks = 0; ks < 4; ks++) {
                uint32_t al[2][4], ag[2][4];
#pragma unroll
                for (int mf = 0; mf < 2; mf++) {
                    uint32_t addr = WL + (uint32_t)(aRow2 + mf * 16) * (WT_DSTR * 2)
                                       + akOff + (uint32_t)(ks * 16 * 2);
                    ldm4(al[mf], addr);
                    ldm4(ag[mf], addr + 64 * WT_DSTR * 2);
                }
                uint32_t bb[4][2];
#pragma unroll
                for (int mt = 0; mt < 2; mt++) {
                    uint32_t addr = GsB
                        + (uint32_t)(bsel * 64 + ks * 16 + bkRow) * (GS_STRIDE * 2)
                        + (uint32_t)(bmOff + mt * 16) * 2;
                    uint32_t tmp[4];
                    ldm4t(tmp, addr);
                    bb[2 * mt][0] = tmp[0]; bb[2 * mt][1] = tmp[1];
                    bb[2 * mt + 1][0] = tmp[2]; bb[2 * mt + 1][1] = tmp[3];
                }
#pragma unroll
                for (int mf = 0; mf < 2; mf++)
#pragma unroll
                    for (int nf = 0; nf < 4; nf++) {
                        mma16816(zl[mf][nf], al[mf], bb[nf]);
                        mma16816(zg[mf][nf], ag[mf], bb[nf]);
                    }
            }

#pragma unroll
            for (int mf = 0; mf < 2; mf++)
#pragma unroll
                for (int nf = 0; nf < 4; nf++)
#pragma unroll
                    for (int q = 0; q < 4; q++) {
                        float v = zl[mf][nf][q] * sigmoidf(zg[mf][nf][q]);
                        omax[mf][nf][q] = fmaxf(omax[mf][nf][q], v);
                    }
        }

        // store out[b, d, t, m]  (scalar stores: NN=883 odd stride, no float2!)
        const int tb = t0 + bsel;
#pragma unroll
        for (int mf = 0; mf < 2; mf++) {
#pragma unroll
            for (int q2 = 0; q2 < 2; q2++) {
                int dd = dw * 32 + mf * 16 + grp + q2 * 8;
                size_t obase = ((size_t)(b * CCH + dd) * T2 + tb) * NN;
#pragma unroll
                for (int nf = 0; nf < 4; nf++) {
                    int m = m0 + mw * 32 + nf * 8 + thr * 2;
                    if (m < NN)     out[obase + m]     = omax[mf][nf][q2 * 2];
                    if (m + 1 < NN) out[obase + m + 1] = omax[mf][nf][q2 * 2 + 1];
                }
            }
        }
    }
}

// ---------------------------------------------------------------------------
extern "C" void kernel_launch(void* const* d_in, const int* in_sizes, int n_in,
                              void* d_out, int out_size) {
    const float* x    = (const float*)d_in[0];
    const float* te   = (const float*)d_in[1];
    const float* se   = (const float*)d_in[2];
    const float* adj  = (const float*)d_in[3];
    const float* Wp   = (const float*)d_in[4];
    const float* bias = (const float*)d_in[5];
    float* out = (float*)d_out;

    cudaFuncSetAttribute(stsgcl_mma_kernel,
                         cudaFuncAttributeMaxDynamicSharedMemorySize, DSMEM_BYTES);

    prep_h_fp16<<<(HP_ELEMS + 255) / 256, 256>>>(x, te, se);
    prep_split_b<<<(int)((BADJ_ELEMS + 255) / 256), 256>>>(adj);

    dim3 grid(NP / 128, NPAIR);   // (7, 160)
    stsgcl_mma_kernel<<<grid, 256, DSMEM_BYTES>>>(Wp, bias, out);
}

// round 6
// speedup vs baseline: 6.6442x; 1.1609x over previous
#include <cuda_runtime.h>
#include <cuda_fp16.h>
#include <cstdint>

// ---------------- problem constants ----------------
#define BB   32
#define CCH  64
#define TT   12
#define T2   10
#define NN   883
#define NP   896            // padded vertex count
#define KP   2688           // 3*NP padded K
#define NKT  42             // K tiles of 64
#define HP_ELEMS  (BB*CCH*TT*NP)
#define BADJ_ELEMS ((size_t)NP*KP)

__device__ __half g_Ah[HP_ELEMS];
__device__ __half g_Bhi[BADJ_ELEMS];
__device__ __half g_Blo[BADJ_ELEMS];

using u64 = unsigned long long;

__device__ __forceinline__ uint32_t smem_u32_of(const void* p) {
    uint32_t a;
    asm("{ .reg .u64 t; cvta.to.shared.u64 t, %1; cvt.u32.u64 %0, t; }" : "=r"(a) : "l"(p));
    return a;
}
__device__ __forceinline__ float sigmoidf(float x) {
    return __fdividef(1.f, 1.f + __expf(-x));
}
#define SW128(o) ((o) ^ (((o) >> 3) & 0x70))

// cp.async
__device__ __forceinline__ void cpa16(uint32_t dst, const void* src) {
    asm volatile("cp.async.cg.shared.global [%0], [%1], 16;" :: "r"(dst), "l"(src));
}
__device__ __forceinline__ void cpa_commit() { asm volatile("cp.async.commit_group;" ::: "memory"); }
template<int N> __device__ __forceinline__ void cpa_wait() {
    asm volatile("cp.async.wait_group %0;" :: "n"(N) : "memory");
}

// warp tensor ops (baseline PTX)
__device__ __forceinline__ void ldm4(uint32_t* r, uint32_t addr) {
    asm volatile("ldmatrix.sync.aligned.m8n8.x4.shared.b16 {%0,%1,%2,%3}, [%4];"
                 : "=r"(r[0]), "=r"(r[1]), "=r"(r[2]), "=r"(r[3]) : "r"(addr));
}
__device__ __forceinline__ void ldm4t(uint32_t* r, uint32_t addr) {
    asm volatile("ldmatrix.sync.aligned.m8n8.x4.trans.shared.b16 {%0,%1,%2,%3}, [%4];"
                 : "=r"(r[0]), "=r"(r[1]), "=r"(r[2]), "=r"(r[3]) : "r"(addr));
}
__device__ __forceinline__ void mma16816(float* d, const uint32_t* a, const uint32_t* b) {
    asm volatile("mma.sync.aligned.m16n8k16.row.col.f32.f16.f16.f32 "
                 "{%0,%1,%2,%3}, {%4,%5,%6,%7}, {%8,%9}, {%0,%1,%2,%3};"
                 : "+f"(d[0]), "+f"(d[1]), "+f"(d[2]), "+f"(d[3])
                 : "r"(a[0]), "r"(a[1]), "r"(a[2]), "r"(a[3]), "r"(b[0]), "r"(b[1]));
}

// ---------------------------------------------------------------------------
// prep 1: padded H -> fp16, vectorized (8 elems / thread, 16B store)
// ---------------------------------------------------------------------------
__global__ void prep_h_fp16(const float* __restrict__ x,
                            const float* __restrict__ te,
                            const float* __restrict__ se) {
    int idx = blockIdx.x * blockDim.x + threadIdx.x;   // over rows*112
    const int ROWS = BB * CCH * TT;
    if (idx >= ROWS * 112) return;
    int n0  = (idx % 112) * 8;
    int row = idx / 112;
    int t = row % TT;
    int c = (row / TT) % CCH;
    const float* xr = x + (size_t)row * NN;
    const float* sr = se + (size_t)c * NN;
    float tv = te[c * TT + t];
    __half h[8];
#pragma unroll
    for (int j = 0; j < 8; j++) {
        int n = n0 + j;
        float v = (n < NN) ? (xr[n] + tv + sr[n]) : 0.f;
        h[j] = __float2half(v);
    }
    *(uint4*)&g_Ah[(size_t)row * NP + n0] = *(const uint4*)h;
}

// ---------------------------------------------------------------------------
// prep 2: B = middle adj rows, fp16 split hi+lo, zero-padded
// ---------------------------------------------------------------------------
__global__ void prep_split_b(const float* __restrict__ adj) {
    size_t idx = (size_t)blockIdx.x * blockDim.x + threadIdx.x;
    if (idx >= BADJ_ELEMS) return;
    int kc = (int)(idx % KP);
    int m  = (int)(idx / KP);
    int j  = kc / NP;
    int kk = kc % NP;
    float v = 0.f;
    if (m < NN && kk < NN)
        v = adj[(size_t)(NN + m) * (3 * NN) + j * NN + kk];
    __half hi = __float2half(v);
    __half lo = __float2half(v - __half2float(hi));
    g_Bhi[idx] = hi;
    g_Blo[idx] = lo;
}

// ---------------------------------------------------------------------------
// main kernel
// GEMM: D[256,128] = A(fp16)[256,2688] x (Bhi+Blo)[2688,128]
//   8 warps, warp tile 64m x 64n (4m x 2n layout); M covers 4 bt groups.
// SMEM: 3 stages x 64KB (A 32K | Bhi 16K | Blo 16K), SW128 rows of 64 fp16
// Epilogue: Gs fp16 [256][136] + Wt fp16 [3g][lin/gate][64d][72c]; tensor GLU
// ---------------------------------------------------------------------------
#define STAGE_BYTES 65536
#define DSMEM_BYTES (3 * STAGE_BYTES)   // 196608
#define GS_STRIDE 136                   // halfs; 272B rows
#define GS_BYTES  (256 * GS_STRIDE * 2) // 69632
#define WT_OFF GS_BYTES
#define WT_DSTR 72                      // halfs; 144B rows

__global__ __launch_bounds__(256, 1)
void stsgcl_mma_kernel(const float* __restrict__ Wp,
                       const float* __restrict__ bias,
                       float* __restrict__ out) {
    extern __shared__ char dsm[];

    const int tid  = threadIdx.x;
    const int m0   = blockIdx.x * 128;
    const int bt0g = blockIdx.y * 4;

    const uint32_t smem = smem_u32_of(dsm);

    // ---- loader precompute: 16 x 16B chunks per stage (64KB / 256 thr) ----
    const char* src0[16];
    uint32_t    dsto[16];
#pragma unroll
    for (int i = 0; i < 16; i++) {
        int L = tid + 256 * i;           // 0..4095 chunk index
        if (L < 2048) {                  // A: 256 rows x 8 chunks
            int r   = L >> 3;
            int c16 = L & 7;
            int g4  = r >> 6;
            int ch  = r & 63;
            int btg = bt0g + g4;
            int bb  = btg / T2;
            int tt  = btg % T2;
            size_t e = ((size_t)(bb * CCH + ch) * TT + tt) * NP + c16 * 8;
            src0[i] = (const char*)g_Ah + e * 2;
            dsto[i] = SW128(r * 128 + c16 * 16);
        } else {                         // Bhi / Blo: 128 rows x 8 chunks each
            int isLo = (L >= 3072);
            int r    = (L >> 3) & 127;
            int c16  = L & 7;
            size_t e = (size_t)(m0 + r) * KP + c16 * 8;
            src0[i] = (const char*)(isLo ? g_Blo : g_Bhi) + e * 2;
            dsto[i] = 32768 + (isLo ? 16384 : 0) + SW128(r * 128 + c16 * 16);
        }
    }

    // ---- prologue: fill 3 stages ----
#pragma unroll
    for (int s = 0; s < 3; s++) {
        uint32_t sb = smem + s * STAGE_BYTES;
#pragma unroll
        for (int i = 0; i < 16; i++) cpa16(sb + dsto[i], src0[i] + (size_t)s * 128);
        cpa_commit();
    }

    // ---- MMA setup (warp 64m x 64n) ----
    const int lane = tid & 31;
    const int wid  = tid >> 5;
    const int wm   = wid & 3;        // m quarter (64 rows of 256)
    const int wn   = wid >> 2;       // n half (64 cols of 128)
    const int rsel = lane & 7;
    const int tsel = lane >> 3;
    const int grp  = lane >> 2;
    const int thr  = lane & 3;

    const int aRowBase = wm * 64 + ((tsel & 1) << 3) + rsel;
    const uint32_t kbeA = (uint32_t)((tsel >> 1) << 4);
    const uint32_t aswz = (uint32_t)((aRowBase & 7) << 4);
    uint32_t aoff[4];
#pragma unroll
    for (int mf = 0; mf < 4; mf++) aoff[mf] = (uint32_t)((aRowBase + mf * 16) * 128);

    const int bRowBase = wn * 64 + ((tsel >> 1) << 3) + rsel;
    const uint32_t kbeB = (uint32_t)((tsel & 1) << 4);
    const uint32_t bswz = (uint32_t)((bRowBase & 7) << 4);
    uint32_t boff[4];
#pragma unroll
    for (int nf2 = 0; nf2 < 4; nf2++) boff[nf2] = (uint32_t)((bRowBase + nf2 * 16) * 128);

    float d[4][8][4];
#pragma unroll
    for (int i = 0; i < 4; i++)
#pragma unroll
        for (int j = 0; j < 8; j++)
#pragma unroll
            for (int q = 0; q < 4; q++) d[i][j][q] = 0.f;

    // ---- main K loop ----
    for (int kt = 0; kt < NKT; kt++) {
        if (kt <= NKT - 3)      cpa_wait<2>();
        else if (kt == NKT - 2) cpa_wait<1>();
        else                    cpa_wait<0>();
        __syncthreads();

        const int sidx = kt - (kt / 3) * 3;
        const uint32_t sb = smem + sidx * STAGE_BYTES;
#pragma unroll
        for (int ks = 0; ks < 4; ks++) {
            const uint32_t kb = (uint32_t)(ks * 32);
            uint32_t a[4][4];
#pragma unroll
            for (int mf = 0; mf < 4; mf++)
                ldm4(a[mf], sb + aoff[mf] + ((kb + kbeA) ^ aswz));
#pragma unroll
            for (int nf2 = 0; nf2 < 4; nf2++) {
                uint32_t addr = sb + 32768 + boff[nf2] + ((kb + kbeB) ^ bswz);
                uint32_t bh[4], bl[4];
                ldm4(bh, addr);
                ldm4(bl, addr + 16384);
#pragma unroll
                for (int mf = 0; mf < 4; mf++) {
                    mma16816(d[mf][2 * nf2],     a[mf], bh);
                    mma16816(d[mf][2 * nf2 + 1], a[mf], bh + 2);
                    mma16816(d[mf][2 * nf2],     a[mf], bl);
                    mma16816(d[mf][2 * nf2 + 1], a[mf], bl + 2);
                }
            }
        }
        __syncthreads();

        if (kt <= NKT - 4) {
            size_t koff = (size_t)(kt + 3) * 128;
#pragma unroll
            for (int i = 0; i < 16; i++) cpa16(sb + dsto[i], src0[i] + koff);
            cpa_commit();
        }
    }

    // ---- stage G (fp16) to Gs[256][136] ----
    {
        __half* Gs = (__half*)dsm;
#pragma unroll
        for (int mf = 0; mf < 4; mf++)
#pragma unroll
            for (int nf = 0; nf < 8; nf++) {
                int row = wm * 64 + mf * 16 + grp;
                int col = wn * 64 + nf * 8 + thr * 2;
                *(__half2*)&Gs[row * GS_STRIDE + col] =
                    __floats2half2_rn(d[mf][nf][0], d[mf][nf][1]);
                *(__half2*)&Gs[(row + 8) * GS_STRIDE + col] =
                    __floats2half2_rn(d[mf][nf][2], d[mf][nf][3]);
            }
    }

    // ---- stage W^T (fp16): Wt[g][sel][d][72], sel 0=lin 1=gate ----
    {
        __half* Wt = (__half*)(dsm + WT_OFF);
#pragma unroll
        for (int it = 0; it < 24; it++) {
            int lin = (tid + 256 * it) * 4;       // over 3*64*128 = 24576
            int g   = lin >> 13;
            int c   = (lin >> 7) & 63;
            int dd  = lin & 127;
            float4 w = *(const float4*)&Wp[((size_t)(g * CCH + c)) * 128 + dd];
            int gsel = g * 2 + (dd >> 6);
            int d0   = dd & 63;
            __half* base = Wt + (size_t)gsel * 64 * WT_DSTR + c;
            base[(d0 + 0) * WT_DSTR] = __float2half(w.x);
            base[(d0 + 1) * WT_DSTR] = __float2half(w.y);
            base[(d0 + 2) * WT_DSTR] = __float2half(w.z);
            base[(d0 + 3) * WT_DSTR] = __float2half(w.w);
        }
    }
    __syncthreads();

    // ---- tensor GLU epilogue: Z[64d,128m] per (bt, g) ----
    const int dw = wid & 1;
    const int mw = wid >> 1;             // 0..3 (32-col m chunks)
    const uint32_t GsB = smem;
    const uint32_t WtB = smem + WT_OFF;

    const int aRow2 = dw * 32 + ((tsel & 1) << 3) + rsel;       // + mf*16
    const uint32_t akOff = (uint32_t)(((tsel >> 1) << 3) * 2);
    const int bkRow = ((tsel & 1) << 3) + rsel;                 // + ks*16 (+bsel*64)
    const int bmOff = mw * 32 + ((tsel >> 1) << 3);             // + mt*16

    for (int bsel = 0; bsel < 4; bsel++) {
        float omax[2][4][4];
#pragma unroll
        for (int mf = 0; mf < 2; mf++)
#pragma unroll
            for (int nf = 0; nf < 4; nf++)
#pragma unroll
                for (int q = 0; q < 4; q++) omax[mf][nf][q] = -3.4e38f;

        for (int g = 0; g < 3; g++) {
            float zl[2][4][4], zg[2][4][4];
#pragma unroll
            for (int mf = 0; mf < 2; mf++) {
                int dbase = dw * 32 + mf * 16 + grp;
                float bl0 = __ldg(&bias[g * 128 + dbase]);
                float bl8 = __ldg(&bias[g * 128 + dbase + 8]);
                float bg0 = __ldg(&bias[g * 128 + 64 + dbase]);
                float bg8 = __ldg(&bias[g * 128 + 64 + dbase + 8]);
#pragma unroll
                for (int nf = 0; nf < 4; nf++) {
                    zl[mf][nf][0] = bl0; zl[mf][nf][1] = bl0;
                    zl[mf][nf][2] = bl8; zl[mf][nf][3] = bl8;
                    zg[mf][nf][0] = bg0; zg[mf][nf][1] = bg0;
                    zg[mf][nf][2] = bg8; zg[mf][nf][3] = bg8;
                }
            }

            const uint32_t WL = WtB + (uint32_t)(g * 2) * 64 * WT_DSTR * 2;
#pragma unroll
            for (int ks = 0; ks < 4; ks++) {
                uint32_t al[2][4], ag[2][4];
#pragma unroll
                for (int mf = 0; mf < 2; mf++) {
                    uint32_t addr = WL + (uint32_t)(aRow2 + mf * 16) * (WT_DSTR * 2)
                                       + akOff + (uint32_t)(ks * 16 * 2);
                    ldm4(al[mf], addr);
                    ldm4(ag[mf], addr + 64 * WT_DSTR * 2);
                }
                uint32_t bb[4][2];
#pragma unroll
                for (int mt = 0; mt < 2; mt++) {
                    uint32_t addr = GsB
                        + (uint32_t)(bsel * 64 + ks * 16 + bkRow) * (GS_STRIDE * 2)
                        + (uint32_t)(bmOff + mt * 16) * 2;
                    uint32_t tmp[4];
                    ldm4t(tmp, addr);
                    bb[2 * mt][0] = tmp[0]; bb[2 * mt][1] = tmp[1];
                    bb[2 * mt + 1][0] = tmp[2]; bb[2 * mt + 1][1] = tmp[3];
                }
#pragma unroll
                for (int mf = 0; mf < 2; mf++)
#pragma unroll
                    for (int nf = 0; nf < 4; nf++) {
                        mma16816(zl[mf][nf], al[mf], bb[nf]);
                        mma16816(zg[mf][nf], ag[mf], bb[nf]);
                    }
            }

#pragma unroll
            for (int mf = 0; mf < 2; mf++)
#pragma unroll
                for (int nf = 0; nf < 4; nf++)
#pragma unroll
                    for (int q = 0; q < 4; q++) {
                        float v = zl[mf][nf][q] * sigmoidf(zg[mf][nf][q]);
                        omax[mf][nf][q] = fmaxf(omax[mf][nf][q], v);
                    }
        }

        // store out[b, d, t, m]  (scalar stores: NN odd stride)
        const int btg = bt0g + bsel;
        const int bb2 = btg / T2;
        const int tb  = btg % T2;
#pragma unroll
        for (int mf = 0; mf < 2; mf++) {
#pragma unroll
            for (int q2 = 0; q2 < 2; q2++) {
                int dd = dw * 32 + mf * 16 + grp + q2 * 8;
                size_t obase = ((size_t)(bb2 * CCH + dd) * T2 + tb) * NN;
#pragma unroll
                for (int nf = 0; nf < 4; nf++) {
                    int m = m0 + mw * 32 + nf * 8 + thr * 2;
                    if (m < NN)     out[obase + m]     = omax[mf][nf][q2 * 2];
                    if (m + 1 < NN) out[obase + m + 1] = omax[mf][nf][q2 * 2 + 1];
                }
            }
        }
    }
}

// ---------------------------------------------------------------------------
extern "C" void kernel_launch(void* const* d_in, const int* in_sizes, int n_in,
                              void* d_out, int out_size) {
    const float* x    = (const float*)d_in[0];
    const float* te   = (const float*)d_in[1];
    const float* se   = (const float*)d_in[2];
    const float* adj  = (const float*)d_in[3];
    const float* Wp   = (const float*)d_in[4];
    const float* bias = (const float*)d_in[5];
    float* out = (float*)d_out;

    cudaFuncSetAttribute(stsgcl_mma_kernel,
                         cudaFuncAttributeMaxDynamicSharedMemorySize, DSMEM_BYTES);

    const int ROWS = BB * CCH * TT;
    prep_h_fp16<<<(ROWS * 112 + 255) / 256, 256>>>(x, te, se);
    prep_split_b<<<(int)((BADJ_ELEMS + 255) / 256), 256>>>(adj);

    dim3 grid(NP / 128, 80);   // (7, 80): m-tiles x bt-quads
    stsgcl_mma_kernel<<<grid, 256, DSMEM_BYTES>>>(Wp, bias, out);
}

// round 7
// speedup vs baseline: 9.7538x; 1.4680x over previous
#include <cuda_runtime.h>
#include <cuda_fp16.h>
#include <cstdint>

// ---------------- problem constants ----------------
#define BB   32
#define CCH  64
#define TT   12
#define T2   10
#define NN   883
#define NP   896            // padded vertex count
#define KP   2688           // 3*NP padded K
#define NKT  42             // K tiles of 64
#define HP_ELEMS  (BB*CCH*TT*NP)
#define BADJ_ELEMS ((size_t)NP*KP)

__device__ __half g_Ah[HP_ELEMS];
__device__ __half g_Bh[BADJ_ELEMS];

using u64 = unsigned long long;

__device__ __forceinline__ uint32_t smem_u32_of(const void* p) {
    uint32_t a;
    asm("{ .reg .u64 t; cvta.to.shared.u64 t, %1; cvt.u32.u64 %0, t; }" : "=r"(a) : "l"(p));
    return a;
}
__device__ __forceinline__ float sigmoidf(float x) {
    return __fdividef(1.f, 1.f + __expf(-x));
}
#define SW128(o) ((o) ^ (((o) >> 3) & 0x70))

// cp.async
__device__ __forceinline__ void cpa16(uint32_t dst, const void* src) {
    asm volatile("cp.async.cg.shared.global [%0], [%1], 16;" :: "r"(dst), "l"(src));
}
__device__ __forceinline__ void cpa_commit() { asm volatile("cp.async.commit_group;" ::: "memory"); }
template<int N> __device__ __forceinline__ void cpa_wait() {
    asm volatile("cp.async.wait_group %0;" :: "n"(N) : "memory");
}

// warp tensor ops (baseline PTX)
__device__ __forceinline__ void ldm4(uint32_t* r, uint32_t addr) {
    asm volatile("ldmatrix.sync.aligned.m8n8.x4.shared.b16 {%0,%1,%2,%3}, [%4];"
                 : "=r"(r[0]), "=r"(r[1]), "=r"(r[2]), "=r"(r[3]) : "r"(addr));
}
__device__ __forceinline__ void ldm4t(uint32_t* r, uint32_t addr) {
    asm volatile("ldmatrix.sync.aligned.m8n8.x4.trans.shared.b16 {%0,%1,%2,%3}, [%4];"
                 : "=r"(r[0]), "=r"(r[1]), "=r"(r[2]), "=r"(r[3]) : "r"(addr));
}
__device__ __forceinline__ void mma16816(float* d, const uint32_t* a, const uint32_t* b) {
    asm volatile("mma.sync.aligned.m16n8k16.row.col.f32.f16.f16.f32 "
                 "{%0,%1,%2,%3}, {%4,%5,%6,%7}, {%8,%9}, {%0,%1,%2,%3};"
                 : "+f"(d[0]), "+f"(d[1]), "+f"(d[2]), "+f"(d[3])
                 : "r"(a[0]), "r"(a[1]), "r"(a[2]), "r"(a[3]), "r"(b[0]), "r"(b[1]));
}

// ---------------------------------------------------------------------------
// prep 1: padded H -> fp16, vectorized (8 elems / thread, 16B store)
// ---------------------------------------------------------------------------
__global__ void prep_h_fp16(const float* __restrict__ x,
                            const float* __restrict__ te,
                            const float* __restrict__ se) {
    int idx = blockIdx.x * blockDim.x + threadIdx.x;   // over rows*112
    const int ROWS = BB * CCH * TT;
    if (idx >= ROWS * 112) return;
    int n0  = (idx % 112) * 8;
    int row = idx / 112;
    int t = row % TT;
    int c = (row / TT) % CCH;
    const float* xr = x + (size_t)row * NN;
    const float* sr = se + (size_t)c * NN;
    float tv = te[c * TT + t];
    __half h[8];
#pragma unroll
    for (int j = 0; j < 8; j++) {
        int n = n0 + j;
        float v = (n < NN) ? (xr[n] + tv + sr[n]) : 0.f;
        h[j] = __float2half(v);
    }
    *(uint4*)&g_Ah[(size_t)row * NP + n0] = *(const uint4*)h;
}

// ---------------------------------------------------------------------------
// prep 2: B = middle adj rows, plain fp16, zero-padded
// ---------------------------------------------------------------------------
__global__ void prep_b_fp16(const float* __restrict__ adj) {
    size_t idx = (size_t)blockIdx.x * blockDim.x + threadIdx.x;
    if (idx >= BADJ_ELEMS) return;
    int kc = (int)(idx % KP);
    int m  = (int)(idx / KP);
    int j  = kc / NP;
    int kk = kc % NP;
    float v = 0.f;
    if (m < NN && kk < NN)
        v = adj[(size_t)(NN + m) * (3 * NN) + j * NN + kk];
    g_Bh[idx] = __float2half(v);
}

// ---------------------------------------------------------------------------
// main kernel
// GEMM: D[256,128] = A(fp16)[256,2688] x B(fp16)[2688,128]
//   8 warps, warp tile 64m x 64n; M covers 4 bt groups.
// SMEM: 4 stages x 48KB (A 32K | B 16K), SW128 rows of 64 fp16
// Epilogue: Gs fp16 [256][136] + Wt fp16 [3g][lin/gate][64d][72c]; tensor GLU
// ---------------------------------------------------------------------------
#define STAGE_BYTES 49152
#define DSMEM_BYTES (4 * STAGE_BYTES)   // 196608
#define GS_STRIDE 136                   // halfs; 272B rows
#define GS_BYTES  (256 * GS_STRIDE * 2) // 69632
#define WT_OFF GS_BYTES
#define WT_DSTR 72                      // halfs; 144B rows

__global__ __launch_bounds__(256, 1)
void stsgcl_mma_kernel(const float* __restrict__ Wp,
                       const float* __restrict__ bias,
                       float* __restrict__ out) {
    extern __shared__ char dsm[];

    const int tid  = threadIdx.x;
    const int m0   = blockIdx.x * 128;
    const int bt0g = blockIdx.y * 4;

    const uint32_t smem = smem_u32_of(dsm);

    // ---- loader precompute: 12 x 16B chunks per stage (48KB / 256 thr) ----
    const char* src0[12];
    uint32_t    dsto[12];
#pragma unroll
    for (int i = 0; i < 12; i++) {
        int L = tid + 256 * i;           // 0..3071 chunk index
        if (L < 2048) {                  // A: 256 rows x 8 chunks
            int r   = L >> 3;
            int c16 = L & 7;
            int g4  = r >> 6;
            int ch  = r & 63;
            int btg = bt0g + g4;
            int bb  = btg / T2;
            int tt  = btg % T2;
            size_t e = ((size_t)(bb * CCH + ch) * TT + tt) * NP + c16 * 8;
            src0[i] = (const char*)g_Ah + e * 2;
            dsto[i] = SW128(r * 128 + c16 * 16);
        } else {                         // B: 128 rows x 8 chunks
            int r    = (L >> 3) & 127;
            int c16  = L & 7;
            size_t e = (size_t)(m0 + r) * KP + c16 * 8;
            src0[i] = (const char*)g_Bh + e * 2;
            dsto[i] = 32768 + SW128(r * 128 + c16 * 16);
        }
    }

    // ---- prologue: fill 4 stages ----
#pragma unroll
    for (int s = 0; s < 4; s++) {
        uint32_t sb = smem + s * STAGE_BYTES;
#pragma unroll
        for (int i = 0; i < 12; i++) cpa16(sb + dsto[i], src0[i] + (size_t)s * 128);
        cpa_commit();
    }

    // ---- MMA setup (warp 64m x 64n) ----
    const int lane = tid & 31;
    const int wid  = tid >> 5;
    const int wm   = wid & 3;        // m quarter
    const int wn   = wid >> 2;       // n half
    const int rsel = lane & 7;
    const int tsel = lane >> 3;
    const int grp  = lane >> 2;
    const int thr  = lane & 3;

    const int aRowBase = wm * 64 + ((tsel & 1) << 3) + rsel;
    const uint32_t kbeA = (uint32_t)((tsel >> 1) << 4);
    const uint32_t aswz = (uint32_t)((aRowBase & 7) << 4);
    uint32_t aoff[4];
#pragma unroll
    for (int mf = 0; mf < 4; mf++) aoff[mf] = (uint32_t)((aRowBase + mf * 16) * 128);

    const int bRowBase = wn * 64 + ((tsel >> 1) << 3) + rsel;
    const uint32_t kbeB = (uint32_t)((tsel & 1) << 4);
    const uint32_t bswz = (uint32_t)((bRowBase & 7) << 4);
    uint32_t boff[4];
#pragma unroll
    for (int nf2 = 0; nf2 < 4; nf2++) boff[nf2] = (uint32_t)((bRowBase + nf2 * 16) * 128);

    float d[4][8][4];
#pragma unroll
    for (int i = 0; i < 4; i++)
#pragma unroll
        for (int j = 0; j < 8; j++)
#pragma unroll
            for (int q = 0; q < 4; q++) d[i][j][q] = 0.f;

    // ---- main K loop ----
    for (int kt = 0; kt < NKT; kt++) {
        if (kt <= NKT - 4)      cpa_wait<3>();
        else if (kt == NKT - 3) cpa_wait<2>();
        else if (kt == NKT - 2) cpa_wait<1>();
        else                    cpa_wait<0>();
        __syncthreads();

        const uint32_t sb = smem + (kt & 3) * STAGE_BYTES;
#pragma unroll
        for (int ks = 0; ks < 4; ks++) {
            const uint32_t kb = (uint32_t)(ks * 32);
            uint32_t a[4][4];
#pragma unroll
            for (int mf = 0; mf < 4; mf++)
                ldm4(a[mf], sb + aoff[mf] + ((kb + kbeA) ^ aswz));
#pragma unroll
            for (int nf2 = 0; nf2 < 4; nf2++) {
                uint32_t bh[4];
                ldm4(bh, sb + 32768 + boff[nf2] + ((kb + kbeB) ^ bswz));
#pragma unroll
                for (int mf = 0; mf < 4; mf++) {
                    mma16816(d[mf][2 * nf2],     a[mf], bh);
                    mma16816(d[mf][2 * nf2 + 1], a[mf], bh + 2);
                }
            }
        }
        __syncthreads();

        if (kt <= NKT - 5) {
            size_t koff = (size_t)(kt + 4) * 128;
#pragma unroll
            for (int i = 0; i < 12; i++) cpa16(sb + dsto[i], src0[i] + koff);
            cpa_commit();
        }
    }

    // ---- stage G (fp16) to Gs[256][136] ----
    {
        __half* Gs = (__half*)dsm;
#pragma unroll
        for (int mf = 0; mf < 4; mf++)
#pragma unroll
            for (int nf = 0; nf < 8; nf++) {
                int row = wm * 64 + mf * 16 + grp;
                int col = wn * 64 + nf * 8 + thr * 2;
                *(__half2*)&Gs[row * GS_STRIDE + col] =
                    __floats2half2_rn(d[mf][nf][0], d[mf][nf][1]);
                *(__half2*)&Gs[(row + 8) * GS_STRIDE + col] =
                    __floats2half2_rn(d[mf][nf][2], d[mf][nf][3]);
            }
    }

    // ---- stage W^T (fp16): Wt[g][sel][d][72], sel 0=lin 1=gate ----
    {
        __half* Wt = (__half*)(dsm + WT_OFF);
#pragma unroll
        for (int it = 0; it < 24; it++) {
            int lin = (tid + 256 * it) * 4;       // over 3*64*128 = 24576
            int g   = lin >> 13;
            int c   = (lin >> 7) & 63;
            int dd  = lin & 127;
            float4 w = *(const float4*)&Wp[((size_t)(g * CCH + c)) * 128 + dd];
            int gsel = g * 2 + (dd >> 6);
            int d0   = dd & 63;
            __half* base = Wt + (size_t)gsel * 64 * WT_DSTR + c;
            base[(d0 + 0) * WT_DSTR] = __float2half(w.x);
            base[(d0 + 1) * WT_DSTR] = __float2half(w.y);
            base[(d0 + 2) * WT_DSTR] = __float2half(w.z);
            base[(d0 + 3) * WT_DSTR] = __float2half(w.w);
        }
    }
    __syncthreads();

    // ---- tensor GLU epilogue: Z[64d,128m] per (bt, g) ----
    const int dw = wid & 1;
    const int mw = wid >> 1;             // 0..3 (32-col m chunks)
    const uint32_t GsB = smem;
    const uint32_t WtB = smem + WT_OFF;

    const int aRow2 = dw * 32 + ((tsel & 1) << 3) + rsel;       // + mf*16
    const uint32_t akOff = (uint32_t)(((tsel >> 1) << 3) * 2);
    const int bkRow = ((tsel & 1) << 3) + rsel;                 // + ks*16 (+bsel*64)
    const int bmOff = mw * 32 + ((tsel >> 1) << 3);             // + mt*16

    for (int bsel = 0; bsel < 4; bsel++) {
        float omax[2][4][4];
#pragma unroll
        for (int mf = 0; mf < 2; mf++)
#pragma unroll
            for (int nf = 0; nf < 4; nf++)
#pragma unroll
                for (int q = 0; q < 4; q++) omax[mf][nf][q] = -3.4e38f;

        for (int g = 0; g < 3; g++) {
            float zl[2][4][4], zg[2][4][4];
#pragma unroll
            for (int mf = 0; mf < 2; mf++) {
                int dbase = dw * 32 + mf * 16 + grp;
                float bl0 = __ldg(&bias[g * 128 + dbase]);
                float bl8 = __ldg(&bias[g * 128 + dbase + 8]);
                float bg0 = __ldg(&bias[g * 128 + 64 + dbase]);
                float bg8 = __ldg(&bias[g * 128 + 64 + dbase + 8]);
#pragma unroll
                for (int nf = 0; nf < 4; nf++) {
                    zl[mf][nf][0] = bl0; zl[mf][nf][1] = bl0;
                    zl[mf][nf][2] = bl8; zl[mf][nf][3] = bl8;
                    zg[mf][nf][0] = bg0; zg[mf][nf][1] = bg0;
                    zg[mf][nf][2] = bg8; zg[mf][nf][3] = bg8;
                }
            }

            const uint32_t WL = WtB + (uint32_t)(g * 2) * 64 * WT_DSTR * 2;
#pragma unroll
            for (int ks = 0; ks < 4; ks++) {
                uint32_t al[2][4], ag[2][4];
#pragma unroll
                for (int mf = 0; mf < 2; mf++) {
                    uint32_t addr = WL + (uint32_t)(aRow2 + mf * 16) * (WT_DSTR * 2)
                                       + akOff + (uint32_t)(ks * 16 * 2);
                    ldm4(al[mf], addr);
                    ldm4(ag[mf], addr + 64 * WT_DSTR * 2);
                }
                uint32_t bb[4][2];
#pragma unroll
                for (int mt = 0; mt < 2; mt++) {
                    uint32_t addr = GsB
                        + (uint32_t)(bsel * 64 + ks * 16 + bkRow) * (GS_STRIDE * 2)
                        + (uint32_t)(bmOff + mt * 16) * 2;
                    uint32_t tmp[4];
                    ldm4t(tmp, addr);
                    bb[2 * mt][0] = tmp[0]; bb[2 * mt][1] = tmp[1];
                    bb[2 * mt + 1][0] = tmp[2]; bb[2 * mt + 1][1] = tmp[3];
                }
#pragma unroll
                for (int mf = 0; mf < 2; mf++)
#pragma unroll
                    for (int nf = 0; nf < 4; nf++) {
                        mma16816(zl[mf][nf], al[mf], bb[nf]);
                        mma16816(zg[mf][nf], ag[mf], bb[nf]);
                    }
            }

#pragma unroll
            for (int mf = 0; mf < 2; mf++)
#pragma unroll
                for (int nf = 0; nf < 4; nf++)
#pragma unroll
                    for (int q = 0; q < 4; q++) {
                        float v = zl[mf][nf][q] * sigmoidf(zg[mf][nf][q]);
                        omax[mf][nf][q] = fmaxf(omax[mf][nf][q], v);
                    }
        }

        // store out[b, d, t, m]  (scalar stores: NN odd stride)
        const int btg = bt0g + bsel;
        const int bb2 = btg / T2;
        const int tb  = btg % T2;
#pragma unroll
        for (int mf = 0; mf < 2; mf++) {
#pragma unroll
            for (int q2 = 0; q2 < 2; q2++) {
                int dd = dw * 32 + mf * 16 + grp + q2 * 8;
                size_t obase = ((size_t)(bb2 * CCH + dd) * T2 + tb) * NN;
#pragma unroll
                for (int nf = 0; nf < 4; nf++) {
                    int m = m0 + mw * 32 + nf * 8 + thr * 2;
                    if (m < NN)     out[obase + m]     = omax[mf][nf][q2 * 2];
                    if (m + 1 < NN) out[obase + m + 1] = omax[mf][nf][q2 * 2 + 1];
                }
            }
        }
    }
}

// ---------------------------------------------------------------------------
extern "C" void kernel_launch(void* const* d_in, const int* in_sizes, int n_in,
                              void* d_out, int out_size) {
    const float* x    = (const float*)d_in[0];
    const float* te   = (const float*)d_in[1];
    const float* se   = (const float*)d_in[2];
    const float* adj  = (const float*)d_in[3];
    const float* Wp   = (const float*)d_in[4];
    const float* bias = (const float*)d_in[5];
    float* out = (float*)d_out;

    cudaFuncSetAttribute(stsgcl_mma_kernel,
                         cudaFuncAttributeMaxDynamicSharedMemorySize, DSMEM_BYTES);

    const int ROWS = BB * CCH * TT;
    prep_h_fp16<<<(ROWS * 112 + 255) / 256, 256>>>(x, te, se);
    prep_b_fp16<<<(int)((BADJ_ELEMS + 255) / 256), 256>>>(adj);

    dim3 grid(NP / 128, 80);   // (7, 80): m-tiles x bt-quads
    stsgcl_mma_kernel<<<grid, 256, DSMEM_BYTES>>>(Wp, bias, out);
}

// round 8
// speedup vs baseline: 9.8657x; 1.0115x over previous
#include <cuda_runtime.h>
#include <cuda_fp16.h>
#include <cstdint>

// ---------------- problem constants ----------------
#define BB   32
#define CCH  64
#define TT   12
#define T2   10
#define NN   883
#define NP   896            // padded vertex count
#define KP   2688           // 3*NP padded K
#define NKT  42             // K tiles of 64
#define HP_ELEMS  (BB*CCH*TT*NP)
#define BADJ_ELEMS ((size_t)NP*KP)

__device__ __half g_Ah[HP_ELEMS];
__device__ __half g_Bh[BADJ_ELEMS];

using u64 = unsigned long long;

__device__ __forceinline__ uint32_t smem_u32_of(const void* p) {
    uint32_t a;
    asm("{ .reg .u64 t; cvta.to.shared.u64 t, %1; cvt.u32.u64 %0, t; }" : "=r"(a) : "l"(p));
    return a;
}
__device__ __forceinline__ float sigmoidf(float x) {
    return __fdividef(1.f, 1.f + __expf(-x));
}
#define SW128(o) ((o) ^ (((o) >> 3) & 0x70))

// cp.async
__device__ __forceinline__ void cpa16(uint32_t dst, const void* src) {
    asm volatile("cp.async.cg.shared.global [%0], [%1], 16;" :: "r"(dst), "l"(src));
}
__device__ __forceinline__ void cpa_commit() { asm volatile("cp.async.commit_group;" ::: "memory"); }
template<int N> __device__ __forceinline__ void cpa_wait() {
    asm volatile("cp.async.wait_group %0;" :: "n"(N) : "memory");
}

// warp tensor ops (baseline PTX)
__device__ __forceinline__ void ldm4(uint32_t* r, uint32_t addr) {
    asm volatile("ldmatrix.sync.aligned.m8n8.x4.shared.b16 {%0,%1,%2,%3}, [%4];"
                 : "=r"(r[0]), "=r"(r[1]), "=r"(r[2]), "=r"(r[3]) : "r"(addr));
}
__device__ __forceinline__ void ldm4t(uint32_t* r, uint32_t addr) {
    asm volatile("ldmatrix.sync.aligned.m8n8.x4.trans.shared.b16 {%0,%1,%2,%3}, [%4];"
                 : "=r"(r[0]), "=r"(r[1]), "=r"(r[2]), "=r"(r[3]) : "r"(addr));
}
__device__ __forceinline__ void mma16816(float* d, const uint32_t* a, const uint32_t* b) {
    asm volatile("mma.sync.aligned.m16n8k16.row.col.f32.f16.f16.f32 "
                 "{%0,%1,%2,%3}, {%4,%5,%6,%7}, {%8,%9}, {%0,%1,%2,%3};"
                 : "+f"(d[0]), "+f"(d[1]), "+f"(d[2]), "+f"(d[3])
                 : "r"(a[0]), "r"(a[1]), "r"(a[2]), "r"(a[3]), "r"(b[0]), "r"(b[1]));
}

// ---------------------------------------------------------------------------
// prep 1: padded H -> fp16, vectorized (8 elems / thread, 16B store)
// ---------------------------------------------------------------------------
__global__ void prep_h_fp16(const float* __restrict__ x,
                            const float* __restrict__ te,
                            const float* __restrict__ se) {
    int idx = blockIdx.x * blockDim.x + threadIdx.x;   // over rows*112
    const int ROWS = BB * CCH * TT;
    if (idx >= ROWS * 112) return;
    int n0  = (idx % 112) * 8;
    int row = idx / 112;
    int t = row % TT;
    int c = (row / TT) % CCH;
    const float* xr = x + (size_t)row * NN;
    const float* sr = se + (size_t)c * NN;
    float tv = te[c * TT + t];
    __half h[8];
#pragma unroll
    for (int j = 0; j < 8; j++) {
        int n = n0 + j;
        float v = (n < NN) ? (xr[n] + tv + sr[n]) : 0.f;
        h[j] = __float2half(v);
    }
    *(uint4*)&g_Ah[(size_t)row * NP + n0] = *(const uint4*)h;
}

// ---------------------------------------------------------------------------
// prep 2: B = middle adj rows, plain fp16, zero-padded
// ---------------------------------------------------------------------------
__global__ void prep_b_fp16(const float* __restrict__ adj) {
    size_t idx = (size_t)blockIdx.x * blockDim.x + threadIdx.x;
    if (idx >= BADJ_ELEMS) return;
    int kc = (int)(idx % KP);
    int m  = (int)(idx / KP);
    int j  = kc / NP;
    int kk = kc % NP;
    float v = 0.f;
    if (m < NN && kk < NN)
        v = adj[(size_t)(NN + m) * (3 * NN) + j * NN + kk];
    g_Bh[idx] = __float2half(v);
}

// ---------------------------------------------------------------------------
// main kernel
// GEMM: D[256,128] = A(fp16)[256,2688] x B(fp16)[2688,128]
//   8 warps, warp tile 64m x 64n; M covers 4 bt groups.
// SMEM: 4 stages x 48KB (A 32K | B 16K), SW128 rows of 64 fp16.
// Single-sync pipeline: iter kt refills stage (kt+3)&3 (consumed at kt-1)
// BEFORE the MMA block, so loads overlap compute and only one barrier/iter.
// Epilogue: Gs fp16 [256][136] + Wt fp16 [3g][lin/gate][64d][72c]; tensor GLU
// ---------------------------------------------------------------------------
#define STAGE_BYTES 49152
#define DSMEM_BYTES (4 * STAGE_BYTES)   // 196608
#define GS_STRIDE 136                   // halfs; 272B rows
#define GS_BYTES  (256 * GS_STRIDE * 2) // 69632
#define WT_OFF GS_BYTES
#define WT_DSTR 72                      // halfs; 144B rows

__global__ __launch_bounds__(256, 1)
void stsgcl_mma_kernel(const float* __restrict__ Wp,
                       const float* __restrict__ bias,
                       float* __restrict__ out) {
    extern __shared__ char dsm[];

    const int tid  = threadIdx.x;
    const int m0   = blockIdx.x * 128;
    const int bt0g = blockIdx.y * 4;

    const uint32_t smem = smem_u32_of(dsm);

    // ---- loader precompute: 12 x 16B chunks per stage (48KB / 256 thr) ----
    const char* src0[12];
    uint32_t    dsto[12];
#pragma unroll
    for (int i = 0; i < 12; i++) {
        int L = tid + 256 * i;           // 0..3071 chunk index
        if (L < 2048) {                  // A: 256 rows x 8 chunks
            int r   = L >> 3;
            int c16 = L & 7;
            int g4  = r >> 6;
            int ch  = r & 63;
            int btg = bt0g + g4;
            int bb  = btg / T2;
            int tt  = btg % T2;
            size_t e = ((size_t)(bb * CCH + ch) * TT + tt) * NP + c16 * 8;
            src0[i] = (const char*)g_Ah + e * 2;
            dsto[i] = SW128(r * 128 + c16 * 16);
        } else {                         // B: 128 rows x 8 chunks
            int r    = (L >> 3) & 127;
            int c16  = L & 7;
            size_t e = (size_t)(m0 + r) * KP + c16 * 8;
            src0[i] = (const char*)g_Bh + e * 2;
            dsto[i] = 32768 + SW128(r * 128 + c16 * 16);
        }
    }

    // ---- prologue: fill stages 0,1,2 with tiles 0,1,2 ----
#pragma unroll
    for (int s = 0; s < 3; s++) {
        uint32_t sb = smem + s * STAGE_BYTES;
#pragma unroll
        for (int i = 0; i < 12; i++) cpa16(sb + dsto[i], src0[i] + (size_t)s * 128);
        cpa_commit();
    }

    // ---- MMA setup (warp 64m x 64n) ----
    const int lane = tid & 31;
    const int wid  = tid >> 5;
    const int wm   = wid & 3;        // m quarter
    const int wn   = wid >> 2;       // n half
    const int rsel = lane & 7;
    const int tsel = lane >> 3;
    const int grp  = lane >> 2;
    const int thr  = lane & 3;

    const int aRowBase = wm * 64 + ((tsel & 1) << 3) + rsel;
    const uint32_t kbeA = (uint32_t)((tsel >> 1) << 4);
    const uint32_t aswz = (uint32_t)((aRowBase & 7) << 4);
    uint32_t aoff[4];
#pragma unroll
    for (int mf = 0; mf < 4; mf++) aoff[mf] = (uint32_t)((aRowBase + mf * 16) * 128);

    const int bRowBase = wn * 64 + ((tsel >> 1) << 3) + rsel;
    const uint32_t kbeB = (uint32_t)((tsel & 1) << 4);
    const uint32_t bswz = (uint32_t)((bRowBase & 7) << 4);
    uint32_t boff[4];
#pragma unroll
    for (int nf2 = 0; nf2 < 4; nf2++) boff[nf2] = (uint32_t)((bRowBase + nf2 * 16) * 128);

    float d[4][8][4];
#pragma unroll
    for (int i = 0; i < 4; i++)
#pragma unroll
        for (int j = 0; j < 8; j++)
#pragma unroll
            for (int q = 0; q < 4; q++) d[i][j][q] = 0.f;

    // ---- main K loop: ONE barrier per iteration ----
    for (int kt = 0; kt < NKT; kt++) {
        if (kt <= NKT - 3)      cpa_wait<2>();
        else if (kt == NKT - 2) cpa_wait<1>();
        else                    cpa_wait<0>();
        __syncthreads();

        // early refill: tile kt+3 -> stage (kt+3)&3 (consumed at iter kt-1)
        if (kt <= NKT - 4) {
            const uint32_t rb = smem + ((kt + 3) & 3) * STAGE_BYTES;
            size_t koff = (size_t)(kt + 3) * 128;
#pragma unroll
            for (int i = 0; i < 12; i++) cpa16(rb + dsto[i], src0[i] + koff);
            cpa_commit();
        }

        const uint32_t sb = smem + (kt & 3) * STAGE_BYTES;
#pragma unroll
        for (int ks = 0; ks < 4; ks++) {
            const uint32_t kb = (uint32_t)(ks * 32);
            uint32_t a[4][4];
#pragma unroll
            for (int mf = 0; mf < 4; mf++)
                ldm4(a[mf], sb + aoff[mf] + ((kb + kbeA) ^ aswz));
#pragma unroll
            for (int nf2 = 0; nf2 < 4; nf2++) {
                uint32_t bh[4];
                ldm4(bh, sb + 32768 + boff[nf2] + ((kb + kbeB) ^ bswz));
#pragma unroll
                for (int mf = 0; mf < 4; mf++) {
                    mma16816(d[mf][2 * nf2],     a[mf], bh);
                    mma16816(d[mf][2 * nf2 + 1], a[mf], bh + 2);
                }
            }
        }
    }
    __syncthreads();   // all MMAs done before Gs overwrites stage smem

    // ---- stage G (fp16) to Gs[256][136] ----
    {
        __half* Gs = (__half*)dsm;
#pragma unroll
        for (int mf = 0; mf < 4; mf++)
#pragma unroll
            for (int nf = 0; nf < 8; nf++) {
                int row = wm * 64 + mf * 16 + grp;
                int col = wn * 64 + nf * 8 + thr * 2;
                *(__half2*)&Gs[row * GS_STRIDE + col] =
                    __floats2half2_rn(d[mf][nf][0], d[mf][nf][1]);
                *(__half2*)&Gs[(row + 8) * GS_STRIDE + col] =
                    __floats2half2_rn(d[mf][nf][2], d[mf][nf][3]);
            }
    }

    // ---- stage W^T (fp16): Wt[g][sel][d][72], sel 0=lin 1=gate ----
    {
        __half* Wt = (__half*)(dsm + WT_OFF);
#pragma unroll
        for (int it = 0; it < 24; it++) {
            int lin = (tid + 256 * it) * 4;       // over 3*64*128 = 24576
            int g   = lin >> 13;
            int c   = (lin >> 7) & 63;
            int dd  = lin & 127;
            float4 w = *(const float4*)&Wp[((size_t)(g * CCH + c)) * 128 + dd];
            int gsel = g * 2 + (dd >> 6);
            int d0   = dd & 63;
            __half* base = Wt + (size_t)gsel * 64 * WT_DSTR + c;
            base[(d0 + 0) * WT_DSTR] = __float2half(w.x);
            base[(d0 + 1) * WT_DSTR] = __float2half(w.y);
            base[(d0 + 2) * WT_DSTR] = __float2half(w.z);
            base[(d0 + 3) * WT_DSTR] = __float2half(w.w);
        }
    }
    __syncthreads();

    // ---- tensor GLU epilogue: Z[64d,128m] per (bt, g) ----
    const int dw = wid & 1;
    const int mw = wid >> 1;             // 0..3 (32-col m chunks)
    const uint32_t GsB = smem;
    const uint32_t WtB = smem + WT_OFF;

    const int aRow2 = dw * 32 + ((tsel & 1) << 3) + rsel;       // + mf*16
    const uint32_t akOff = (uint32_t)(((tsel >> 1) << 3) * 2);
    const int bkRow = ((tsel & 1) << 3) + rsel;                 // + ks*16 (+bsel*64)
    const int bmOff = mw * 32 + ((tsel >> 1) << 3);             // + mt*16

    for (int bsel = 0; bsel < 4; bsel++) {
        float omax[2][4][4];
#pragma unroll
        for (int mf = 0; mf < 2; mf++)
#pragma unroll
            for (int nf = 0; nf < 4; nf++)
#pragma unroll
                for (int q = 0; q < 4; q++) omax[mf][nf][q] = -3.4e38f;

        for (int g = 0; g < 3; g++) {
            float zl[2][4][4], zg[2][4][4];
#pragma unroll
            for (int mf = 0; mf < 2; mf++) {
                int dbase = dw * 32 + mf * 16 + grp;
                float bl0 = __ldg(&bias[g * 128 + dbase]);
                float bl8 = __ldg(&bias[g * 128 + dbase + 8]);
                float bg0 = __ldg(&bias[g * 128 + 64 + dbase]);
                float bg8 = __ldg(&bias[g * 128 + 64 + dbase + 8]);
#pragma unroll
                for (int nf = 0; nf < 4; nf++) {
                    zl[mf][nf][0] = bl0; zl[mf][nf][1] = bl0;
                    zl[mf][nf][2] = bl8; zl[mf][nf][3] = bl8;
                    zg[mf][nf][0] = bg0; zg[mf][nf][1] = bg0;
                    zg[mf][nf][2] = bg8; zg[mf][nf][3] = bg8;
                }
            }

            const uint32_t WL = WtB + (uint32_t)(g * 2) * 64 * WT_DSTR * 2;
#pragma unroll
            for (int ks = 0; ks < 4; ks++) {
                uint32_t al[2][4], ag[2][4];
#pragma unroll
                for (int mf = 0; mf < 2; mf++) {
                    uint32_t addr = WL + (uint32_t)(aRow2 + mf * 16) * (WT_DSTR * 2)
                                       + akOff + (uint32_t)(ks * 16 * 2);
                    ldm4(al[mf], addr);
                    ldm4(ag[mf], addr + 64 * WT_DSTR * 2);
                }
                uint32_t bb[4][2];
#pragma unroll
                for (int mt = 0; mt < 2; mt++) {
                    uint32_t addr = GsB
                        + (uint32_t)(bsel * 64 + ks * 16 + bkRow) * (GS_STRIDE * 2)
                        + (uint32_t)(bmOff + mt * 16) * 2;
                    uint32_t tmp[4];
                    ldm4t(tmp, addr);
                    bb[2 * mt][0] = tmp[0]; bb[2 * mt][1] = tmp[1];
                    bb[2 * mt + 1][0] = tmp[2]; bb[2 * mt + 1][1] = tmp[3];
                }
#pragma unroll
                for (int mf = 0; mf < 2; mf++)
#pragma unroll
                    for (int nf = 0; nf < 4; nf++) {
                        mma16816(zl[mf][nf], al[mf], bb[nf]);
                        mma16816(zg[mf][nf], ag[mf], bb[nf]);
                    }
            }

#pragma unroll
            for (int mf = 0; mf < 2; mf++)
#pragma unroll
                for (int nf = 0; nf < 4; nf++)
#pragma unroll
                    for (int q = 0; q < 4; q++) {
                        float v = zl[mf][nf][q] * sigmoidf(zg[mf][nf][q]);
                        omax[mf][nf][q] = fmaxf(omax[mf][nf][q], v);
                    }
        }

        // store out[b, d, t, m]  (scalar stores: NN odd stride)
        const int btg = bt0g + bsel;
        const int bb2 = btg / T2;
        const int tb  = btg % T2;
#pragma unroll
        for (int mf = 0; mf < 2; mf++) {
#pragma unroll
            for (int q2 = 0; q2 < 2; q2++) {
                int dd = dw * 32 + mf * 16 + grp + q2 * 8;
                size_t obase = ((size_t)(bb2 * CCH + dd) * T2 + tb) * NN;
#pragma unroll
                for (int nf = 0; nf < 4; nf++) {
                    int m = m0 + mw * 32 + nf * 8 + thr * 2;
                    if (m < NN)     out[obase + m]     = omax[mf][nf][q2 * 2];
                    if (m + 1 < NN) out[obase + m + 1] = omax[mf][nf][q2 * 2 + 1];
                }
            }
        }
    }
}

// ---------------------------------------------------------------------------
extern "C" void kernel_launch(void* const* d_in, const int* in_sizes, int n_in,
                              void* d_out, int out_size) {
    const float* x    = (const float*)d_in[0];
    const float* te   = (const float*)d_in[1];
    const float* se   = (const float*)d_in[2];
    const float* adj  = (const float*)d_in[3];
    const float* Wp   = (const float*)d_in[4];
    const float* bias = (const float*)d_in[5];
    float* out = (float*)d_out;

    cudaFuncSetAttribute(stsgcl_mma_kernel,
                         cudaFuncAttributeMaxDynamicSharedMemorySize, DSMEM_BYTES);

    const int ROWS = BB * CCH * TT;
    prep_h_fp16<<<(ROWS * 112 + 255) / 256, 256>>>(x, te, se);
    prep_b_fp16<<<(int)((BADJ_ELEMS + 255) / 256), 256>>>(adj);

    dim3 grid(NP / 128, 80);   // (7, 80): m-tiles x bt-quads
    stsgcl_mma_kernel<<<grid, 256, DSMEM_BYTES>>>(Wp, bias, out);
}

// round 9
// speedup vs baseline: 10.0323x; 1.0169x over previous
#include <cuda_runtime.h>
#include <cuda_fp16.h>
#include <cstdint>

// ---------------- problem constants ----------------
#define BB   32
#define CCH  64
#define TT   12
#define T2   10
#define NN   883
#define NP   896            // padded vertex count
#define KP   2688           // 3*NP padded K
#define NKT  42             // K tiles of 64
#define HP_ELEMS  (BB*CCH*TT*NP)
#define BADJ_ELEMS ((size_t)NP*KP)
#define NTHREADS 512

__device__ __half g_Ah[HP_ELEMS];
__device__ __half g_Bh[BADJ_ELEMS];

using u64 = unsigned long long;

__device__ __forceinline__ uint32_t smem_u32_of(const void* p) {
    uint32_t a;
    asm("{ .reg .u64 t; cvta.to.shared.u64 t, %1; cvt.u32.u64 %0, t; }" : "=r"(a) : "l"(p));
    return a;
}
__device__ __forceinline__ float sigmoidf(float x) {
    return __fdividef(1.f, 1.f + __expf(-x));
}
#define SW128(o) ((o) ^ (((o) >> 3) & 0x70))

// cp.async
__device__ __forceinline__ void cpa16(uint32_t dst, const void* src) {
    asm volatile("cp.async.cg.shared.global [%0], [%1], 16;" :: "r"(dst), "l"(src));
}
__device__ __forceinline__ void cpa_commit() { asm volatile("cp.async.commit_group;" ::: "memory"); }
template<int N> __device__ __forceinline__ void cpa_wait() {
    asm volatile("cp.async.wait_group %0;" :: "n"(N) : "memory");
}

// warp tensor ops (baseline PTX)
__device__ __forceinline__ void ldm4(uint32_t* r, uint32_t addr) {
    asm volatile("ldmatrix.sync.aligned.m8n8.x4.shared.b16 {%0,%1,%2,%3}, [%4];"
                 : "=r"(r[0]), "=r"(r[1]), "=r"(r[2]), "=r"(r[3]) : "r"(addr));
}
__device__ __forceinline__ void ldm4t(uint32_t* r, uint32_t addr) {
    asm volatile("ldmatrix.sync.aligned.m8n8.x4.trans.shared.b16 {%0,%1,%2,%3}, [%4];"
                 : "=r"(r[0]), "=r"(r[1]), "=r"(r[2]), "=r"(r[3]) : "r"(addr));
}
__device__ __forceinline__ void mma16816(float* d, const uint32_t* a, const uint32_t* b) {
    asm volatile("mma.sync.aligned.m16n8k16.row.col.f32.f16.f16.f32 "
                 "{%0,%1,%2,%3}, {%4,%5,%6,%7}, {%8,%9}, {%0,%1,%2,%3};"
                 : "+f"(d[0]), "+f"(d[1]), "+f"(d[2]), "+f"(d[3])
                 : "r"(a[0]), "r"(a[1]), "r"(a[2]), "r"(a[3]), "r"(b[0]), "r"(b[1]));
}

// ---------------------------------------------------------------------------
// prep 1: padded H -> fp16, vectorized (8 elems / thread, 16B store)
// ---------------------------------------------------------------------------
__global__ void prep_h_fp16(const float* __restrict__ x,
                            const float* __restrict__ te,
                            const float* __restrict__ se) {
    int idx = blockIdx.x * blockDim.x + threadIdx.x;   // over rows*112
    const int ROWS = BB * CCH * TT;
    if (idx >= ROWS * 112) return;
    int n0  = (idx % 112) * 8;
    int row = idx / 112;
    int t = row % TT;
    int c = (row / TT) % CCH;
    const float* xr = x + (size_t)row * NN;
    const float* sr = se + (size_t)c * NN;
    float tv = te[c * TT + t];
    __half h[8];
#pragma unroll
    for (int j = 0; j < 8; j++) {
        int n = n0 + j;
        float v = (n < NN) ? (xr[n] + tv + sr[n]) : 0.f;
        h[j] = __float2half(v);
    }
    *(uint4*)&g_Ah[(size_t)row * NP + n0] = *(const uint4*)h;
}

// ---------------------------------------------------------------------------
// prep 2: B = middle adj rows, plain fp16, zero-padded
// ---------------------------------------------------------------------------
__global__ void prep_b_fp16(const float* __restrict__ adj) {
    size_t idx = (size_t)blockIdx.x * blockDim.x + threadIdx.x;
    if (idx >= BADJ_ELEMS) return;
    int kc = (int)(idx % KP);
    int m  = (int)(idx / KP);
    int j  = kc / NP;
    int kk = kc % NP;
    float v = 0.f;
    if (m < NN && kk < NN)
        v = adj[(size_t)(NN + m) * (3 * NN) + j * NN + kk];
    g_Bh[idx] = __float2half(v);
}

// ---------------------------------------------------------------------------
// main kernel (512 threads, 16 warps, 4 warps/SMSP)
// GEMM: D[256,128] = A(fp16)[256,2688] x B(fp16)[2688,128]
//   warp tile 64m x 32n (4m x 4n warp grid); M covers 4 bt groups.
// SMEM: 4 stages x 48KB (A 32K | B 16K), SW128 rows of 64 fp16.
// Single-sync pipeline: iter kt refills stage (kt+3)&3 before the MMA block.
// Epilogue: Gs fp16 [256][136] + Wt fp16 [3g][lin/gate][64d][72c]; tensor GLU,
//   warp-halves process bsel pairs in parallel (2 iterations).
// ---------------------------------------------------------------------------
#define STAGE_BYTES 49152
#define DSMEM_BYTES (4 * STAGE_BYTES)   // 196608
#define GS_STRIDE 136                   // halfs; 272B rows
#define GS_BYTES  (256 * GS_STRIDE * 2) // 69632
#define WT_OFF GS_BYTES
#define WT_DSTR 72                      // halfs; 144B rows

__global__ __launch_bounds__(NTHREADS, 1)
void stsgcl_mma_kernel(const float* __restrict__ Wp,
                       const float* __restrict__ bias,
                       float* __restrict__ out) {
    extern __shared__ char dsm[];

    const int tid  = threadIdx.x;
    const int m0   = blockIdx.x * 128;
    const int bt0g = blockIdx.y * 4;

    const uint32_t smem = smem_u32_of(dsm);

    // ---- loader precompute: 6 x 16B chunks per stage (48KB / 512 thr) ----
    // chunks L = tid + 512*i:  i in 0..3 -> A (L < 2048), i in 4..5 -> B
    const char* src0[6];
    uint32_t    dsto[6];
#pragma unroll
    for (int i = 0; i < 6; i++) {
        int L = tid + NTHREADS * i;
        if (L < 2048) {                  // A: 256 rows x 8 chunks
            int r   = L >> 3;
            int c16 = L & 7;
            int g4  = r >> 6;
            int ch  = r & 63;
            int btg = bt0g + g4;
            int bb  = btg / T2;
            int tt  = btg % T2;
            size_t e = ((size_t)(bb * CCH + ch) * TT + tt) * NP + c16 * 8;
            src0[i] = (const char*)g_Ah + e * 2;
            dsto[i] = SW128(r * 128 + c16 * 16);
        } else {                         // B: 128 rows x 8 chunks
            int r    = (L >> 3) & 127;
            int c16  = L & 7;
            size_t e = (size_t)(m0 + r) * KP + c16 * 8;
            src0[i] = (const char*)g_Bh + e * 2;
            dsto[i] = 32768 + SW128(r * 128 + c16 * 16);
        }
    }

    // ---- prologue: fill stages 0,1,2 with tiles 0,1,2 ----
#pragma unroll
    for (int s = 0; s < 3; s++) {
        uint32_t sb = smem + s * STAGE_BYTES;
#pragma unroll
        for (int i = 0; i < 6; i++) cpa16(sb + dsto[i], src0[i] + (size_t)s * 128);
        cpa_commit();
    }

    // ---- MMA setup (warp 64m x 32n; wm = wid&3, wn = wid>>2) ----
    const int lane = tid & 31;
    const int wid  = tid >> 5;
    const int wm   = wid & 3;        // m quarter (64 rows of 256)
    const int wn   = wid >> 2;       // n quarter (32 cols of 128)
    const int rsel = lane & 7;
    const int tsel = lane >> 3;
    const int grp  = lane >> 2;
    const int thr  = lane & 3;

    const int aRowBase = wm * 64 + ((tsel & 1) << 3) + rsel;
    const uint32_t kbeA = (uint32_t)((tsel >> 1) << 4);
    const uint32_t aswz = (uint32_t)((aRowBase & 7) << 4);
    uint32_t aoff[4];
#pragma unroll
    for (int mf = 0; mf < 4; mf++) aoff[mf] = (uint32_t)((aRowBase + mf * 16) * 128);

    const int bRowBase = wn * 32 + ((tsel >> 1) << 3) + rsel;
    const uint32_t kbeB = (uint32_t)((tsel & 1) << 4);
    const uint32_t bswz = (uint32_t)((bRowBase & 7) << 4);
    uint32_t boff[2];
#pragma unroll
    for (int nf2 = 0; nf2 < 2; nf2++) boff[nf2] = (uint32_t)((bRowBase + nf2 * 16) * 128);

    float d[4][4][4];
#pragma unroll
    for (int i = 0; i < 4; i++)
#pragma unroll
        for (int j = 0; j < 4; j++)
#pragma unroll
            for (int q = 0; q < 4; q++) d[i][j][q] = 0.f;

    // ---- main K loop: one barrier per iteration ----
    for (int kt = 0; kt < NKT; kt++) {
        if (kt <= NKT - 3)      cpa_wait<2>();
        else if (kt == NKT - 2) cpa_wait<1>();
        else                    cpa_wait<0>();
        __syncthreads();

        // early refill: tile kt+3 -> stage (kt+3)&3 (consumed at iter kt-1)
        if (kt <= NKT - 4) {
            const uint32_t rb = smem + ((kt + 3) & 3) * STAGE_BYTES;
            size_t koff = (size_t)(kt + 3) * 128;
#pragma unroll
            for (int i = 0; i < 6; i++) cpa16(rb + dsto[i], src0[i] + koff);
            cpa_commit();
        }

        const uint32_t sb = smem + (kt & 3) * STAGE_BYTES;
#pragma unroll
        for (int ks = 0; ks < 4; ks++) {
            const uint32_t kb = (uint32_t)(ks * 32);
            uint32_t a[4][4];
#pragma unroll
            for (int mf = 0; mf < 4; mf++)
                ldm4(a[mf], sb + aoff[mf] + ((kb + kbeA) ^ aswz));
#pragma unroll
            for (int nf2 = 0; nf2 < 2; nf2++) {
                uint32_t bh[4];
                ldm4(bh, sb + 32768 + boff[nf2] + ((kb + kbeB) ^ bswz));
#pragma unroll
                for (int mf = 0; mf < 4; mf++) {
                    mma16816(d[mf][2 * nf2],     a[mf], bh);
                    mma16816(d[mf][2 * nf2 + 1], a[mf], bh + 2);
                }
            }
        }
    }
    __syncthreads();   // all MMAs done before Gs overwrites stage smem

    // ---- stage G (fp16) to Gs[256][136] ----
    {
        __half* Gs = (__half*)dsm;
#pragma unroll
        for (int mf = 0; mf < 4; mf++)
#pragma unroll
            for (int nf = 0; nf < 4; nf++) {
                int row = wm * 64 + mf * 16 + grp;
                int col = wn * 32 + nf * 8 + thr * 2;
                *(__half2*)&Gs[row * GS_STRIDE + col] =
                    __floats2half2_rn(d[mf][nf][0], d[mf][nf][1]);
                *(__half2*)&Gs[(row + 8) * GS_STRIDE + col] =
                    __floats2half2_rn(d[mf][nf][2], d[mf][nf][3]);
            }
    }

    // ---- stage W^T (fp16): Wt[g][sel][d][72], sel 0=lin 1=gate ----
    {
        __half* Wt = (__half*)(dsm + WT_OFF);
#pragma unroll
        for (int it = 0; it < 12; it++) {
            int lin = (tid + NTHREADS * it) * 4;   // over 3*64*128 = 24576
            int g   = lin >> 13;
            int c   = (lin >> 7) & 63;
            int dd  = lin & 127;
            float4 w = *(const float4*)&Wp[((size_t)(g * CCH + c)) * 128 + dd];
            int gsel = g * 2 + (dd >> 6);
            int d0   = dd & 63;
            __half* base = Wt + (size_t)gsel * 64 * WT_DSTR + c;
            base[(d0 + 0) * WT_DSTR] = __float2half(w.x);
            base[(d0 + 1) * WT_DSTR] = __float2half(w.y);
            base[(d0 + 2) * WT_DSTR] = __float2half(w.z);
            base[(d0 + 3) * WT_DSTR] = __float2half(w.w);
        }
    }
    __syncthreads();

    // ---- tensor GLU epilogue: Z[64d,128m] per (bt, g) ----
    // 16 warps: bq = wid>>3 selects bsel pair; within half: dw, mw as before.
    const int bq = wid >> 3;
    const int dw = wid & 1;
    const int mw = (wid >> 1) & 3;       // 0..3 (32-col m chunks)
    const uint32_t GsB = smem;
    const uint32_t WtB = smem + WT_OFF;

    const int aRow2 = dw * 32 + ((tsel & 1) << 3) + rsel;       // + mf*16
    const uint32_t akOff = (uint32_t)(((tsel >> 1) << 3) * 2);
    const int bkRow = ((tsel & 1) << 3) + rsel;                 // + ks*16 (+bsel*64)
    const int bmOff = mw * 32 + ((tsel >> 1) << 3);             // + mt*16

    for (int it = 0; it < 2; it++) {
        const int bsel = bq * 2 + it;
        float omax[2][4][4];
#pragma unroll
        for (int mf = 0; mf < 2; mf++)
#pragma unroll
            for (int nf = 0; nf < 4; nf++)
#pragma unroll
                for (int q = 0; q < 4; q++) omax[mf][nf][q] = -3.4e38f;

        for (int g = 0; g < 3; g++) {
            float zl[2][4][4], zg[2][4][4];
#pragma unroll
            for (int mf = 0; mf < 2; mf++) {
                int dbase = dw * 32 + mf * 16 + grp;
                float bl0 = __ldg(&bias[g * 128 + dbase]);
                float bl8 = __ldg(&bias[g * 128 + dbase + 8]);
                float bg0 = __ldg(&bias[g * 128 + 64 + dbase]);
                float bg8 = __ldg(&bias[g * 128 + 64 + dbase + 8]);
#pragma unroll
                for (int nf = 0; nf < 4; nf++) {
                    zl[mf][nf][0] = bl0; zl[mf][nf][1] = bl0;
                    zl[mf][nf][2] = bl8; zl[mf][nf][3] = bl8;
                    zg[mf][nf][0] = bg0; zg[mf][nf][1] = bg0;
                    zg[mf][nf][2] = bg8; zg[mf][nf][3] = bg8;
                }
            }

            const uint32_t WL = WtB + (uint32_t)(g * 2) * 64 * WT_DSTR * 2;
#pragma unroll
            for (int ks = 0; ks < 4; ks++) {
                uint32_t al[2][4], ag[2][4];
#pragma unroll
                for (int mf = 0; mf < 2; mf++) {
                    uint32_t addr = WL + (uint32_t)(aRow2 + mf * 16) * (WT_DSTR * 2)
                                       + akOff + (uint32_t)(ks * 16 * 2);
                    ldm4(al[mf], addr);
                    ldm4(ag[mf], addr + 64 * WT_DSTR * 2);
                }
                uint32_t bb[4][2];
#pragma unroll
                for (int mt = 0; mt < 2; mt++) {
                    uint32_t addr = GsB
                        + (uint32_t)(bsel * 64 + ks * 16 + bkRow) * (GS_STRIDE * 2)
                        + (uint32_t)(bmOff + mt * 16) * 2;
                    uint32_t tmp[4];
                    ldm4t(tmp, addr);
                    bb[2 * mt][0] = tmp[0]; bb[2 * mt][1] = tmp[1];
                    bb[2 * mt + 1][0] = tmp[2]; bb[2 * mt + 1][1] = tmp[3];
                }
#pragma unroll
                for (int mf = 0; mf < 2; mf++)
#pragma unroll
                    for (int nf = 0; nf < 4; nf++) {
                        mma16816(zl[mf][nf], al[mf], bb[nf]);
                        mma16816(zg[mf][nf], ag[mf], bb[nf]);
                    }
            }

#pragma unroll
            for (int mf = 0; mf < 2; mf++)
#pragma unroll
                for (int nf = 0; nf < 4; nf++)
#pragma unroll
                    for (int q = 0; q < 4; q++) {
                        float v = zl[mf][nf][q] * sigmoidf(zg[mf][nf][q]);
                        omax[mf][nf][q] = fmaxf(omax[mf][nf][q], v);
                    }
        }

        // store out[b, d, t, m]  (scalar stores: NN odd stride)
        const int btg = bt0g + bsel;
        const int bb2 = btg / T2;
        const int tb  = btg % T2;
#pragma unroll
        for (int mf = 0; mf < 2; mf++) {
#pragma unroll
            for (int q2 = 0; q2 < 2; q2++) {
                int dd = dw * 32 + mf * 16 + grp + q2 * 8;
                size_t obase = ((size_t)(bb2 * CCH + dd) * T2 + tb) * NN;
#pragma unroll
                for (int nf = 0; nf < 4; nf++) {
                    int m = m0 + mw * 32 + nf * 8 + thr * 2;
                    if (m < NN)     out[obase + m]     = omax[mf][nf][q2 * 2];
                    if (m + 1 < NN) out[obase + m + 1] = omax[mf][nf][q2 * 2 + 1];
                }
            }
        }
    }
}

// ---------------------------------------------------------------------------
extern "C" void kernel_launch(void* const* d_in, const int* in_sizes, int n_in,
                              void* d_out, int out_size) {
    const float* x    = (const float*)d_in[0];
    const float* te   = (const float*)d_in[1];
    const float* se   = (const float*)d_in[2];
    const float* adj  = (const float*)d_in[3];
    const float* Wp   = (const float*)d_in[4];
    const float* bias = (const float*)d_in[5];
    float* out = (float*)d_out;

    cudaFuncSetAttribute(stsgcl_mma_kernel,
                         cudaFuncAttributeMaxDynamicSharedMemorySize, DSMEM_BYTES);

    const int ROWS = BB * CCH * TT;
    prep_h_fp16<<<(ROWS * 112 + 255) / 256, 256>>>(x, te, se);
    prep_b_fp16<<<(int)((BADJ_ELEMS + 255) / 256), 256>>>(adj);

    dim3 grid(NP / 128, 80);   // (7, 80): m-tiles x bt-quads
    stsgcl_mma_kernel<<<grid, NTHREADS, DSMEM_BYTES>>>(Wp, bias, out);
}